// round 11
// baseline (speedup 1.0000x reference)
#include <cuda_runtime.h>
#include <cuda_bf16.h>
#include <cuda_fp16.h>
#include <math.h>
#include <stdint.h>

// Problem dims (fixed)
#define BB   2
#define SQ   512
#define SKK  512
#define EE   512
#define HH   256
#define MR   1024            // B*SQ = B*SK
#define NTOT (BB*SQ*SKK)     // 524288

// ---------------- scratch (device globals; no allocation allowed) -------------
__device__ float g_qf [MR*HH];
__device__ float g_kf [MR*HH];
__device__ float g_qp [MR*HH];
__device__ float g_vq [MR*HH];
__device__ float g_kpT[HH*MR];   // [H][B*SK]
__device__ float g_vkT[HH*MR];   // [H][B*SK]
// fp16 weight images: word layout [layer][k][nw] (nw = n/2, f16x2)
__device__ __align__(16) uint32_t g_Wh[2 * 256 * 128];

// SMEM map (byte offsets from 1024-aligned base)
#define SM_A   0u        // 64 rows x 512B  (fp16 A) = 32KB
#define SM_BW  32768u    // 8 warps x 2 bufs x 4KB = 64KB (warp-private B rings)
#define SM_VEC 98304u    // vectors + reductions (8KB)
#define SMEM_BYTES (106496 + 1024)

// ---------------- PTX helpers --------------------------------------------------
__device__ __forceinline__ uint32_t smem_u32(const void* p) {
    return (uint32_t)__cvta_generic_to_shared(p);
}
__device__ __forceinline__ void ldsm_x4(uint32_t (&r)[4], uint32_t addr) {
    asm volatile("ldmatrix.sync.aligned.m8n8.x4.shared.b16 {%0,%1,%2,%3}, [%4];"
        : "=r"(r[0]), "=r"(r[1]), "=r"(r[2]), "=r"(r[3]) : "r"(addr));
}
__device__ __forceinline__ void ldsm_x4_t(uint32_t (&r)[4], uint32_t addr) {
    asm volatile("ldmatrix.sync.aligned.m8n8.x4.trans.shared.b16 {%0,%1,%2,%3}, [%4];"
        : "=r"(r[0]), "=r"(r[1]), "=r"(r[2]), "=r"(r[3]) : "r"(addr));
}
__device__ __forceinline__ void mma_f16(float (&d)[4], const uint32_t (&a)[4],
                                        uint32_t b0, uint32_t b1) {
    asm volatile("mma.sync.aligned.m16n8k16.row.col.f32.f16.f16.f32 "
        "{%0,%1,%2,%3}, {%4,%5,%6,%7}, {%8,%9}, {%0,%1,%2,%3};"
        : "+f"(d[0]), "+f"(d[1]), "+f"(d[2]), "+f"(d[3])
        : "r"(a[0]), "r"(a[1]), "r"(a[2]), "r"(a[3]), "r"(b0), "r"(b1));
}
__device__ __forceinline__ unsigned long long pack_dup(float a) {
    unsigned long long r;
    asm("mov.b64 %0, {%1, %1};" : "=l"(r) : "f"(a));
    return r;
}
__device__ __forceinline__ void unpack2(unsigned long long v, float& lo, float& hi) {
    asm("mov.b64 {%0, %1}, %2;" : "=f"(lo), "=f"(hi) : "l"(v));
}
__device__ __forceinline__ void ffma2(unsigned long long& acc, unsigned long long a,
                                      unsigned long long b) {
    asm("fma.rn.f32x2 %0, %1, %2, %0;" : "+l"(acc) : "l"(a), "l"(b));
}

// ---------------- small math helpers ------------------------------------------
// pack two floats as f16x2 (v0 -> low half, v1 -> high half)
__device__ __forceinline__ uint32_t f16x2bits(float v0, float v1) {
    __half2 h = __floats2half2_rn(v0, v1);
    return *reinterpret_cast<uint32_t*>(&h);
}
__device__ __forceinline__ float softplusf(float x) {
    if (x > 20.f) return x;
    return log1pf(expf(x));
}

// ---------------- weight convert prologue (fp16) -------------------------------
__global__ __launch_bounds__(256)
void wsplit_kernel(const float* __restrict__ W2, const float* __restrict__ W3)
{
    int idx = blockIdx.x * 256 + threadIdx.x;     // 0..65535
    int layer = idx >> 15;
    int rem   = idx & 32767;
    int k  = rem >> 7;          // 0..255
    int nw = rem & 127;         // 0..127
    const float* W = layer ? W3 : W2;
    float v0 = W[k * 256 + nw * 2];
    float v1 = W[k * 256 + nw * 2 + 1];
    g_Wh[idx] = f16x2bits(v0, v1);
}

// ---------------- prologue: batched 1024x256 projection GEMM (f32x2) ----------
struct ProjJob {
    const float* A; const float* W; const float* bias; float* C;
    int wrow0; int doRelu; int doTrans;
};

__global__ __launch_bounds__(256)
void proj_batch_kernel(ProjJob j0, ProjJob j1, ProjJob j2, ProjJob j3, int K)
{
    ProjJob jb = (blockIdx.z == 0) ? j0 : (blockIdx.z == 1) ? j1 :
                 (blockIdx.z == 2) ? j2 : j3;
    __shared__ float As[16][36];
    __shared__ float Ws[16][68];
    const int tid = threadIdx.x;
    const int m0  = blockIdx.y * 32;
    const int n0  = blockIdx.x * 64;
    const int ty  = tid >> 4, tx = tid & 15;

    unsigned long long acc2[2][2] = {{0ull, 0ull}, {0ull, 0ull}};
    const int nch = K >> 4;
    for (int ch = 0; ch < nch; ch++) {
        const int kc = ch << 4;
        __syncthreads();
        {
            int e = tid;        int m = e >> 4, kk = e & 15;
            As[kk][m] = jb.A[(m0 + m) * K + kc + kk];
            e = tid + 256;      m = e >> 4;     kk = e & 15;
            As[kk][m] = jb.A[(m0 + m) * K + kc + kk];
        }
        #pragma unroll
        for (int i = 0; i < 4; i++) {
            int e = tid + (i << 8);
            int kk = e >> 6, n = e & 63;
            Ws[kk][n] = jb.W[(jb.wrow0 + kc + kk) * 256 + n0 + n];
        }
        __syncthreads();
        #pragma unroll
        for (int kk = 0; kk < 16; kk++) {
            unsigned long long a0d = pack_dup(As[kk][ty * 2]);
            unsigned long long a1d = pack_dup(As[kk][ty * 2 + 1]);
            unsigned long long w01 = *(const unsigned long long*)&Ws[kk][tx * 4];
            unsigned long long w23 = *(const unsigned long long*)&Ws[kk][tx * 4 + 2];
            ffma2(acc2[0][0], a0d, w01);
            ffma2(acc2[0][1], a0d, w23);
            ffma2(acc2[1][0], a1d, w01);
            ffma2(acc2[1][1], a1d, w23);
        }
    }
    #pragma unroll
    for (int i = 0; i < 2; i++) {
        float vout[4];
        unpack2(acc2[i][0], vout[0], vout[1]);
        unpack2(acc2[i][1], vout[2], vout[3]);
        const int r = m0 + ty * 2 + i;
        #pragma unroll
        for (int j = 0; j < 4; j++) {
            const int n = n0 + tx * 4 + j;
            float v = vout[j] + (jb.bias ? jb.bias[n] : 0.f);
            if (jb.doRelu) v = fmaxf(v, 0.f);
            if (jb.doTrans) jb.C[n * MR + r] = v;
            else            jb.C[r * 256 + n] = v;
        }
    }
}

// ---------------- main pairwise-MLP kernel (fp16 mma, warp-private B rings) ----

// warp copies ITS 128B/row slice of one 32-row chunk into its private buffer.
// srcbase = WhL + chunk*16384 + warpN*128;  dstbuf = warp ring half (4KB).
__device__ __forceinline__ void cp_own(const char* __restrict__ srcbase,
                                       uint32_t dstbuf, int lane)
{
    const char* s = srcbase + lane * 512;
    uint32_t d  = dstbuf + (uint32_t)lane * 128u;
    uint32_t sw = (uint32_t)(lane & 7) << 4;
    #pragma unroll
    for (int i = 0; i < 8; i++) {
        uint32_t off = ((uint32_t)(i << 4)) ^ sw;
        asm volatile("cp.async.cg.shared.global [%0], [%1], 16;"
                     :: "r"(d + off), "l"(s + i * 16));
    }
    asm volatile("cp.async.commit_group;" ::: "memory");
}

// build 2 adjacent 16B units (g0, g0+1) of one A row: j0 = 8*g0 + quad*2
__device__ __forceinline__ void a_store_units(char* smp, int m, int quad, int g0,
                                              float v0, float v1, float v2, float v3)
{
    char* arow = smp + (uint32_t)m * 512u;
    uint32_t off0 = (uint32_t)(((g0 ^ (m & 7)) << 4) + quad * 4);
    *(uint32_t*)(arow + SM_A + off0) = f16x2bits(v0, v1);
    uint32_t off1 = (uint32_t)((((g0 + 1) ^ (m & 7)) << 4) + quad * 4);
    *(uint32_t*)(arow + SM_A + off1) = f16x2bits(v2, v3);
}

// One 64x256x256 fp16 GEMM: acc += A(smem, shared) @ W(warp-private ring).
// Caller pre-issued cp_own for chunks 0,1 of WhL. NO __syncthreads inside.
__device__ __forceinline__ void gemm_pass(const char* __restrict__ WhL,
                                          uint32_t bwbase, int warpN,
                                          const uint32_t a_row[2],
                                          const uint32_t a_sw[2],
                                          const uint32_t boff[4],
                                          int rit, int koff, int lane,
                                          float (&acc)[2][8][4])
{
    const uint32_t bw_rit = bwbase + (uint32_t)rit * 128u;
    #pragma unroll 1
    for (int c = 0; c < 8; c++) {
        if (c < 7) { asm volatile("cp.async.wait_group 1;" ::: "memory"); }
        else       { asm volatile("cp.async.wait_group 0;" ::: "memory"); }
        const uint32_t bb = bw_rit + (uint32_t)((c & 1) * 4096);
        #pragma unroll
        for (int s = 0; s < 2; s++) {
            const int k16 = c * 2 + s;
            uint32_t ah[2][4];
            #pragma unroll
            for (int mt = 0; mt < 2; mt++) {
                uint32_t unit = (uint32_t)(k16 * 2 + koff);
                ldsm_x4(ah[mt], a_row[mt] + ((unit ^ a_sw[mt]) << 4));
            }
            const uint32_t brow = bb + (uint32_t)(s * 2048);
            #pragma unroll
            for (int np = 0; np < 4; np++) {
                uint32_t bh[4];
                ldsm_x4_t(bh, brow + boff[np]);
                #pragma unroll
                for (int mt = 0; mt < 2; mt++) {
                    mma_f16(acc[mt][np * 2],     ah[mt], bh[0], bh[1]);
                    mma_f16(acc[mt][np * 2 + 1], ah[mt], bh[2], bh[3]);
                }
            }
        }
        // refill this buffer with chunk c+2 (we just finished reading chunk c)
        if (c < 6)
            cp_own(WhL + (c + 2) * 16384 + warpN * 128,
                   bwbase + (uint32_t)((c & 1) * 4096), lane);
    }
}

__global__ __launch_bounds__(256, 2)
void pair_mma_kernel(const float* __restrict__ b1,  const float* __restrict__ b2,
                     const float* __restrict__ b3,  const float* __restrict__ Wf,
                     const float* __restrict__ bfp, const float* __restrict__ bv1,
                     const float* __restrict__ Wv2, const float* __restrict__ bv2,
                     float* __restrict__ out)
{
    extern __shared__ char smraw[];
    const uint32_t smbase = smem_u32(smraw);
    const uint32_t abase  = (smbase + 1023u) & ~1023u;
    char* smp = smraw + (abase - smbase);
    float* qpb  = (float*)(smp + SM_VEC);
    float* vqb  = qpb + 256;
    float* b2s  = vqb + 256;
    float* b3s  = b2s + 256;
    float* wfs  = b3s + 256;
    float* wv2s = wfs + 256;
    float* red  = wv2s + 256;   // 256 floats: [row(64)][warpN(4)]
    float* vred = red + 256;    // 256 floats: [key(64)][p(4)]

    const int tid   = threadIdx.x;
    const int lane  = tid & 31;
    const int w     = tid >> 5;
    const int warpM = w & 1, warpN = w >> 1;  // 2 x 4 warp grid
    const int quad  = tid >> 6;               // 0..3
    const int m     = tid & 63;               // key within tile
    const int bid = blockIdx.x;
    const int kt  = bid & 7;
    const int q   = (bid >> 3) & 511;
    const int b   = bid >> 12;
    const int k0  = kt << 6;
    const int rowb  = b * SKK + k0 + m;
    const int lbase = (b * SQ + q) * SKK + k0;

    // MMA lane decomposition + hoisted addresses
    const int rit  = (lane & 7) | (((lane >> 3) & 1) << 3);
    const int koff = lane >> 4;
    const uint32_t bwbase = abase + SM_BW + (uint32_t)w * 8192u;
    uint32_t a_row[2], a_sw[2];
    #pragma unroll
    for (int mt = 0; mt < 2; mt++) {
        int rr = warpM * 32 + mt * 16 + rit;
        a_row[mt] = abase + (uint32_t)rr * 512u;
        a_sw[mt]  = (uint32_t)(rr & 7);
    }
    uint32_t boff[4];
    #pragma unroll
    for (int np = 0; np < 4; np++)
        boff[np] = (uint32_t)(((np * 2 + koff) ^ (rit & 7)) << 4);

    // pre-issue W2 chunks 0,1 into this warp's private ring
    cp_own((const char*)g_Wh + warpN * 128,         bwbase,         lane);
    cp_own((const char*)g_Wh + 16384 + warpN * 128, bwbase + 4096u, lane);

    // vectors (256 threads, one element of each vector per thread)
    {
        const int r = (b * SQ + q) * HH;
        qpb[tid]  = g_qp[r + tid] + b1[tid];
        vqb[tid]  = g_vq[r + tid] + bv1[tid];
        b2s[tid]  = b2[tid];
        b3s[tid]  = b3[tid];
        wfs[tid]  = Wf[tid];
        wv2s[tid] = Wv2[tid];
    }
    __syncthreads();   // B1: vectors ready

    // ---- build ALL of A (h0) + variance dot ----
    {
        #pragma unroll 4
        for (int gg = 0; gg < 16; gg++) {
            int g0 = gg * 2;
            int j0 = 8 * g0 + quad * 2;
            float v0 = fmaxf(qpb[j0]     + g_kpT[j0 * MR + rowb],       0.f);
            float v1 = fmaxf(qpb[j0 + 1] + g_kpT[(j0 + 1) * MR + rowb], 0.f);
            float v2 = fmaxf(qpb[j0 + 8] + g_kpT[(j0 + 8) * MR + rowb], 0.f);
            float v3 = fmaxf(qpb[j0 + 9] + g_kpT[(j0 + 9) * MR + rowb], 0.f);
            a_store_units(smp, m, quad, g0, v0, v1, v2, v3);
        }
        float vacc = 0.f;
        #pragma unroll 8
        for (int jj = 0; jj < 64; jj++) {
            int j = quad * 64 + jj;
            vacc = fmaf(fmaxf(vqb[j] + g_vkT[j * MR + rowb], 0.f), wv2s[j], vacc);
        }
        vred[m * 4 + quad] = vacc;
    }
    __syncthreads();   // B2: A + vred ready

    // variance finalize (warps 0,1 only — small skew, others start GEMM1)
    if (tid < 64) {
        float s = vred[tid * 4] + vred[tid * 4 + 1] + vred[tid * 4 + 2] + vred[tid * 4 + 3]
                  + bv2[0];
        out[NTOT + lbase + tid] = softplusf(s);
    }

    // ---- GEMM 1: D = h0 @ W2 (barrier-free; warp-private W ring) ----
    float acc[2][8][4];
    #pragma unroll
    for (int i = 0; i < 2; i++)
        #pragma unroll
        for (int j = 0; j < 8; j++)
            #pragma unroll
            for (int e = 0; e < 4; e++) acc[i][j][e] = 0.f;
    gemm_pass((const char*)g_Wh, bwbase, warpN,
              a_row, a_sw, boff, rit, koff, lane, acc);

    // pre-issue W3 chunks 0,1 (warp-private buffers; own GEMM1 reads done)
    cp_own((const char*)g_Wh + 131072 + warpN * 128,         bwbase,         lane);
    cp_own((const char*)g_Wh + 131072 + 16384 + warpN * 128, bwbase + 4096u, lane);

    __syncthreads();   // B3: all warps finished reading h0

    // ---- epilogue 1: h1 = relu(D + b2) -> A buffer (fp16) ----
    {
        const int g  = lane >> 2;
        const int tg = lane & 3;
        #pragma unroll
        for (int mt = 0; mt < 2; mt++) {
            int r0 = warpM * 32 + mt * 16 + g;
            int r1 = r0 + 8;
            uint32_t row0 = (uint32_t)r0 * 512u;
            uint32_t row1 = (uint32_t)r1 * 512u;
            #pragma unroll
            for (int nt = 0; nt < 8; nt++) {
                int c0 = warpN * 64 + nt * 8 + tg * 2;
                float b20 = b2s[c0], b21 = b2s[c0 + 1];
                float v00 = fmaxf(acc[mt][nt][0] + b20, 0.f);
                float v01 = fmaxf(acc[mt][nt][1] + b21, 0.f);
                float v10 = fmaxf(acc[mt][nt][2] + b20, 0.f);
                float v11 = fmaxf(acc[mt][nt][3] + b21, 0.f);
                uint32_t unit = (uint32_t)(c0 >> 3);
                uint32_t o0 = row0 + ((unit ^ (uint32_t)(r0 & 7)) << 4) + (uint32_t)(tg * 4);
                uint32_t o1 = row1 + ((unit ^ (uint32_t)(r1 & 7)) << 4) + (uint32_t)(tg * 4);
                *(uint32_t*)(smp + SM_A + o0) = f16x2bits(v00, v01);
                *(uint32_t*)(smp + SM_A + o1) = f16x2bits(v10, v11);
            }
        }
    }
    __syncthreads();   // B4: h1 ready

    // ---- GEMM 2: D = h1 @ W3 (barrier-free) ----
    #pragma unroll
    for (int i = 0; i < 2; i++)
        #pragma unroll
        for (int j = 0; j < 8; j++)
            #pragma unroll
            for (int e = 0; e < 4; e++) acc[i][j][e] = 0.f;
    gemm_pass((const char*)g_Wh + 131072, bwbase, warpN,
              a_row, a_sw, boff, rit, koff, lane, acc);

    // ---- epilogue 2: logit = relu(D + b3) . Wf, cross-warp reduce ----
    {
        const int g  = lane >> 2;
        const int tg = lane & 3;
        #pragma unroll
        for (int mt = 0; mt < 2; mt++) {
            float lg0 = 0.f, lg1 = 0.f;
            #pragma unroll
            for (int nt = 0; nt < 8; nt++) {
                int c0 = warpN * 64 + nt * 8 + tg * 2;
                float b30 = b3s[c0], b31 = b3s[c0 + 1];
                float w0  = wfs[c0], w1  = wfs[c0 + 1];
                lg0 = fmaf(fmaxf(acc[mt][nt][0] + b30, 0.f), w0, lg0);
                lg0 = fmaf(fmaxf(acc[mt][nt][1] + b31, 0.f), w1, lg0);
                lg1 = fmaf(fmaxf(acc[mt][nt][2] + b30, 0.f), w0, lg1);
                lg1 = fmaf(fmaxf(acc[mt][nt][3] + b31, 0.f), w1, lg1);
            }
            lg0 += __shfl_xor_sync(0xffffffffu, lg0, 1);
            lg0 += __shfl_xor_sync(0xffffffffu, lg0, 2);
            lg1 += __shfl_xor_sync(0xffffffffu, lg1, 1);
            lg1 += __shfl_xor_sync(0xffffffffu, lg1, 2);
            if (tg == 0) {
                int r0 = warpM * 32 + mt * 16 + g;
                red[r0 * 4 + warpN]       = lg0;
                red[(r0 + 8) * 4 + warpN] = lg1;
            }
        }
    }
    __syncthreads();   // B5
    if (tid < 64) {
        float s = red[tid * 4] + red[tid * 4 + 1] + red[tid * 4 + 2] + red[tid * 4 + 3]
                  + bfp[0];
        out[lbase + tid] = s;
    }
}

// ---------------- launcher -----------------------------------------------------
extern "C" void kernel_launch(void* const* d_in, const int* in_sizes, int n_in,
                              void* d_out, int out_size)
{
    const float* query = (const float*)d_in[0];
    const float* key   = (const float*)d_in[1];
    const float* Wqe   = (const float*)d_in[2];
    const float* bqe   = (const float*)d_in[3];
    const float* Wke   = (const float*)d_in[4];
    const float* bke   = (const float*)d_in[5];
    const float* W1    = (const float*)d_in[6];
    const float* b1    = (const float*)d_in[7];
    const float* W2    = (const float*)d_in[8];
    const float* b2    = (const float*)d_in[9];
    const float* W3    = (const float*)d_in[10];
    const float* b3    = (const float*)d_in[11];
    const float* Wf    = (const float*)d_in[12];
    const float* bf    = (const float*)d_in[13];
    const float* Wv1   = (const float*)d_in[14];
    const float* bv1   = (const float*)d_in[15];
    const float* Wv2   = (const float*)d_in[16];
    const float* bv2   = (const float*)d_in[17];
    float* out = (float*)d_out;

    void *p_qf, *p_kf, *p_qp, *p_vq, *p_kpT, *p_vkT;
    cudaGetSymbolAddress(&p_qf,  g_qf);
    cudaGetSymbolAddress(&p_kf,  g_kf);
    cudaGetSymbolAddress(&p_qp,  g_qp);
    cudaGetSymbolAddress(&p_vq,  g_vq);
    cudaGetSymbolAddress(&p_kpT, g_kpT);
    cudaGetSymbolAddress(&p_vkT, g_vkT);

    // weight convert (independent of projections)
    wsplit_kernel<<<256, 256>>>(W2, W3);

    // encoders: qf = relu(query@Wqe+bqe), kf = relu(key@Wke+bke)
    ProjJob e0 { query, Wqe, bqe, (float*)p_qf, 0, 1, 0 };
    ProjJob e1 { key,   Wke, bke, (float*)p_kf, 0, 1, 0 };
    proj_batch_kernel<<<dim3(4, 32, 2), 256>>>(e0, e1, e0, e0, EE);

    // stage-2 projections
    ProjJob s0 { (const float*)p_qf, W1,  nullptr, (float*)p_qp,  0,   0, 0 };
    ProjJob s1 { (const float*)p_kf, W1,  nullptr, (float*)p_kpT, 256, 0, 1 };
    ProjJob s2 { (const float*)p_qf, Wv1, nullptr, (float*)p_vq,  0,   0, 0 };
    ProjJob s3 { (const float*)p_kf, Wv1, nullptr, (float*)p_vkT, 256, 0, 1 };
    proj_batch_kernel<<<dim3(4, 32, 4), 256>>>(s0, s1, s2, s3, HH);

    // main fused pairwise-MLP kernel (fp16 mma, warp-private W rings, 2 CTAs/SM)
    cudaFuncSetAttribute(pair_mma_kernel,
                         cudaFuncAttributeMaxDynamicSharedMemorySize, SMEM_BYTES);
    pair_mma_kernel<<<BB * SQ * (SKK / 64), 256, SMEM_BYTES>>>(
        b1, b2, b3, Wf, bf, bv1, Wv2, bv2, out);
}

// round 12
// speedup vs baseline: 2.2988x; 2.2988x over previous
#include <cuda_runtime.h>
#include <cuda_bf16.h>
#include <cuda_fp16.h>
#include <math.h>
#include <stdint.h>

// Problem dims (fixed)
#define BB   2
#define SQ   512
#define SKK  512
#define EE   512
#define HH   256
#define MR   1024            // B*SQ = B*SK
#define NTOT (BB*SQ*SKK)     // 524288

// ---------------- scratch (device globals; no allocation allowed) -------------
__device__ float g_qf [MR*HH];
__device__ float g_kf [MR*HH];
__device__ float g_qp [MR*HH];
__device__ float g_vq [MR*HH];
__device__ float g_kpT[HH*MR];   // [H][B*SK]
__device__ float g_vkT[HH*MR];   // [H][B*SK]
// fp16 weight images: word layout [layer][k][nw] (nw = n/2, f16x2)
__device__ __align__(16) uint32_t g_Wh[2 * 256 * 128];

// SMEM map (byte offsets from 1024-aligned base)  -- main kernel
#define SM_A   0u        // 128 rows x 512B  (fp16 A) = 64KB
#define SM_W   65536u    // 256 rows x 512B  (full weight layer, fp16) = 128KB
#define SM_VEC 196608u
#define SMEM_BYTES (206848 + 1024)

// ---------------- PTX helpers --------------------------------------------------
__device__ __forceinline__ uint32_t smem_u32(const void* p) {
    return (uint32_t)__cvta_generic_to_shared(p);
}
__device__ __forceinline__ void ldsm_x4(uint32_t (&r)[4], uint32_t addr) {
    asm volatile("ldmatrix.sync.aligned.m8n8.x4.shared.b16 {%0,%1,%2,%3}, [%4];"
        : "=r"(r[0]), "=r"(r[1]), "=r"(r[2]), "=r"(r[3]) : "r"(addr));
}
__device__ __forceinline__ void ldsm_x4_t(uint32_t (&r)[4], uint32_t addr) {
    asm volatile("ldmatrix.sync.aligned.m8n8.x4.trans.shared.b16 {%0,%1,%2,%3}, [%4];"
        : "=r"(r[0]), "=r"(r[1]), "=r"(r[2]), "=r"(r[3]) : "r"(addr));
}
__device__ __forceinline__ void mma_f16(float (&d)[4], const uint32_t (&a)[4],
                                        uint32_t b0, uint32_t b1) {
    asm volatile("mma.sync.aligned.m16n8k16.row.col.f32.f16.f16.f32 "
        "{%0,%1,%2,%3}, {%4,%5,%6,%7}, {%8,%9}, {%0,%1,%2,%3};"
        : "+f"(d[0]), "+f"(d[1]), "+f"(d[2]), "+f"(d[3])
        : "r"(a[0]), "r"(a[1]), "r"(a[2]), "r"(a[3]), "r"(b0), "r"(b1));
}
__device__ __forceinline__ unsigned long long pack_dup(float a) {
    unsigned long long r;
    asm("mov.b64 %0, {%1, %1};" : "=l"(r) : "f"(a));
    return r;
}
__device__ __forceinline__ void unpack2(unsigned long long v, float& lo, float& hi) {
    asm("mov.b64 {%0, %1}, %2;" : "=f"(lo), "=f"(hi) : "l"(v));
}
__device__ __forceinline__ void ffma2(unsigned long long& acc, unsigned long long a,
                                      unsigned long long b) {
    asm("fma.rn.f32x2 %0, %1, %2, %0;" : "+l"(acc) : "l"(a), "l"(b));
}

// ---------------- small math helpers ------------------------------------------
__device__ __forceinline__ uint32_t f16x2bits(float v0, float v1) {
    __half2 h = __floats2half2_rn(v0, v1);
    return *reinterpret_cast<uint32_t*>(&h);
}
__device__ __forceinline__ float softplusf(float x) {
    if (x > 20.f) return x;
    return log1pf(expf(x));
}

// ---------------- weight convert prologue (fp16) -------------------------------
__global__ __launch_bounds__(256)
void wsplit_kernel(const float* __restrict__ W2, const float* __restrict__ W3)
{
    int idx = blockIdx.x * 256 + threadIdx.x;     // 0..65535
    int layer = idx >> 15;
    int rem   = idx & 32767;
    int k  = rem >> 7;          // 0..255
    int nw = rem & 127;         // 0..127
    const float* W = layer ? W3 : W2;
    float v0 = W[k * 256 + nw * 2];
    float v1 = W[k * 256 + nw * 2 + 1];
    g_Wh[idx] = f16x2bits(v0, v1);
}

// ---------------- prologue: batched 1024x256 projection GEMM -------------------
// cp.async double-buffered A/W chunk staging; one barrier per K-chunk.
struct ProjJob {
    const float* A; const float* W; const float* bias; float* C;
    int wrow0; int doRelu; int doTrans;
};

#define PAS_LD 20   // As row stride (floats): 16 data + 4 pad (80B, 16B-aligned)

__device__ __forceinline__ void proj_stage_chunk(const float* __restrict__ A,
                                                 const float* __restrict__ W,
                                                 int K, int wrow0, int m0, int n0,
                                                 int kc, uint32_t asb, uint32_t wsb,
                                                 int tid)
{
    // A chunk: 32 rows x 16 k floats (64B/row = 4 x 16B); 128 ops, tid<128
    if (tid < 128) {
        int m = tid >> 2, seg = tid & 3;
        const float* src = A + (m0 + m) * K + kc + seg * 4;
        uint32_t dst = asb + (uint32_t)(m * PAS_LD + seg * 4) * 4u;
        asm volatile("cp.async.cg.shared.global [%0], [%1], 16;"
                     :: "r"(dst), "l"(src));
    }
    // W chunk: 16 k-rows x 64 n floats (256B/row = 16 x 16B); 256 ops
    {
        int kk = tid >> 4, seg = tid & 15;
        const float* src = W + (wrow0 + kc + kk) * 256 + n0 + seg * 4;
        uint32_t dst = wsb + (uint32_t)(kk * 64 + seg * 4) * 4u;
        asm volatile("cp.async.cg.shared.global [%0], [%1], 16;"
                     :: "r"(dst), "l"(src));
    }
    asm volatile("cp.async.commit_group;" ::: "memory");
}

__global__ __launch_bounds__(256)
void proj_batch_kernel(ProjJob j0, ProjJob j1, ProjJob j2, ProjJob j3, int K)
{
    ProjJob jb = (blockIdx.z == 0) ? j0 : (blockIdx.z == 1) ? j1 :
                 (blockIdx.z == 2) ? j2 : j3;
    __shared__ __align__(16) float As[2][32 * PAS_LD];
    __shared__ __align__(16) float Ws[2][16 * 64];
    const int tid = threadIdx.x;
    const int m0  = blockIdx.y * 32;
    const int n0  = blockIdx.x * 64;
    const int ty  = tid >> 4, tx = tid & 15;

    const uint32_t asb0 = smem_u32(&As[0][0]), asb1 = smem_u32(&As[1][0]);
    const uint32_t wsb0 = smem_u32(&Ws[0][0]), wsb1 = smem_u32(&Ws[1][0]);

    unsigned long long acc2[2][2] = {{0ull, 0ull}, {0ull, 0ull}};
    const int nch = K >> 4;

    // stage chunk 0 into buf 0
    proj_stage_chunk(jb.A, jb.W, K, jb.wrow0, m0, n0, 0, asb0, wsb0, tid);

    for (int ch = 0; ch < nch; ch++) {
        // stage chunk ch+1 into the other buffer
        if (ch + 1 < nch)
            proj_stage_chunk(jb.A, jb.W, K, jb.wrow0, m0, n0, (ch + 1) << 4,
                             (ch & 1) ? asb0 : asb1, (ch & 1) ? wsb0 : wsb1, tid);
        if (ch + 1 < nch) { asm volatile("cp.async.wait_group 1;" ::: "memory"); }
        else              { asm volatile("cp.async.wait_group 0;" ::: "memory"); }
        __syncthreads();

        const float* Ab = As[ch & 1];
        const float* Wb = Ws[ch & 1];
        #pragma unroll
        for (int kk = 0; kk < 16; kk++) {
            unsigned long long a0d = pack_dup(Ab[(ty * 2) * PAS_LD + kk]);
            unsigned long long a1d = pack_dup(Ab[(ty * 2 + 1) * PAS_LD + kk]);
            unsigned long long w01 = *(const unsigned long long*)&Wb[kk * 64 + tx * 4];
            unsigned long long w23 = *(const unsigned long long*)&Wb[kk * 64 + tx * 4 + 2];
            ffma2(acc2[0][0], a0d, w01);
            ffma2(acc2[0][1], a0d, w23);
            ffma2(acc2[1][0], a1d, w01);
            ffma2(acc2[1][1], a1d, w23);
        }
        __syncthreads();   // buffer (ch&1) free for reuse at ch+2
    }
    #pragma unroll
    for (int i = 0; i < 2; i++) {
        float vout[4];
        unpack2(acc2[i][0], vout[0], vout[1]);
        unpack2(acc2[i][1], vout[2], vout[3]);
        const int r = m0 + ty * 2 + i;
        #pragma unroll
        for (int j = 0; j < 4; j++) {
            const int n = n0 + tx * 4 + j;
            float v = vout[j] + (jb.bias ? jb.bias[n] : 0.f);
            if (jb.doRelu) v = fmaxf(v, 0.f);
            if (jb.doTrans) jb.C[n * MR + r] = v;
            else            jb.C[r * 256 + n] = v;
        }
    }
}

// ---------------- main pairwise-MLP kernel (R8: fp16 mma, barrier-free GEMM) ---

// copy one full weight layer (128KB, 256 rows x 512B) into SM_W with swizzle
__device__ __forceinline__ void cp_layer(const char* __restrict__ src,
                                         uint32_t dstbase, int tid)
{
    #pragma unroll
    for (int i = 0; i < 16; i++) {
        int e = tid + i * 512;                 // 0..8191
        int k = e >> 5, u = e & 31;            // row (0..255), 16B unit
        uint32_t d = dstbase + (uint32_t)k * 512u + (uint32_t)((u ^ (k & 7)) << 4);
        asm volatile("cp.async.cg.shared.global [%0], [%1], 16;"
                     :: "r"(d), "l"(src + e * 16));
    }
    asm volatile("cp.async.commit_group;" ::: "memory");
}

// build 2 adjacent 16B units (g0, g0+1) of one A row: j0 = 8*g0 + quad*2
__device__ __forceinline__ void a_store_units(char* smp, int m, int quad, int g0,
                                              float v0, float v1, float v2, float v3)
{
    char* arow = smp + (uint32_t)m * 512u;
    uint32_t off0 = (uint32_t)(((g0 ^ (m & 7)) << 4) + quad * 4);
    *(uint32_t*)(arow + SM_A + off0) = f16x2bits(v0, v1);
    uint32_t off1 = (uint32_t)((((g0 + 1) ^ (m & 7)) << 4) + quad * 4);
    *(uint32_t*)(arow + SM_A + off1) = f16x2bits(v2, v3);
}

// One 128x256x256 fp16 GEMM: acc += A(smem) @ W(smem, full layer resident).
// Register-pipelined fragments; NO barriers, NO waits — pure MMA stream.
__device__ __forceinline__ void gemm_pass(uint32_t abase,
                                          int warpM, int warpN, int lane,
                                          float (&acc)[2][8][4])
{
    const int rit  = (lane & 7) | (((lane >> 3) & 1) << 3); // row within 16-tile
    const int koff = lane >> 4;                              // 0/1: unit select
    uint32_t a_row[2]; uint32_t a_sw[2];
    #pragma unroll
    for (int mt = 0; mt < 2; mt++) {
        int rr = warpM * 32 + mt * 16 + rit;
        a_row[mt] = abase + (uint32_t)rr * 512u;
        a_sw[mt]  = (uint32_t)(rr & 7);
    }
    const uint32_t ksw = (uint32_t)(rit & 7);
    uint32_t boff[4];
    #pragma unroll
    for (int np = 0; np < 4; np++) {
        uint32_t nunit = (uint32_t)(warpN * 8 + np * 2 + koff);
        boff[np] = ((nunit ^ ksw) << 4);
    }
    const uint32_t browbase = abase + SM_W + (uint32_t)rit * 512u;

    // fragment double buffers: parity = k16 & 1
    uint32_t aF[2][2][4];   // [parity][mt]
    uint32_t bF[2][2][4];   // [parity][np 0..1]
    #pragma unroll
    for (int mt = 0; mt < 2; mt++)
        ldsm_x4(aF[0][mt], a_row[mt] + (((uint32_t)koff ^ a_sw[mt]) << 4));
    ldsm_x4_t(bF[0][0], browbase + boff[0]);
    ldsm_x4_t(bF[0][1], browbase + boff[1]);

    #pragma unroll
    for (int k16 = 0; k16 < 16; k16++) {
        const int s = k16 & 1;
        uint32_t bT[2][4];
        const uint32_t brow = browbase + (uint32_t)k16 * 8192u;
        ldsm_x4_t(bT[0], brow + boff[2]);
        ldsm_x4_t(bT[1], brow + boff[3]);

        #pragma unroll
        for (int mt = 0; mt < 2; mt++) {
            mma_f16(acc[mt][0], aF[s][mt], bF[s][0][0], bF[s][0][1]);
            mma_f16(acc[mt][1], aF[s][mt], bF[s][0][2], bF[s][0][3]);
            mma_f16(acc[mt][2], aF[s][mt], bF[s][1][0], bF[s][1][1]);
            mma_f16(acc[mt][3], aF[s][mt], bF[s][1][2], bF[s][1][3]);
        }

        if (k16 < 15) {
            #pragma unroll
            for (int mt = 0; mt < 2; mt++) {
                uint32_t unit = (uint32_t)((k16 + 1) * 2 + koff);
                ldsm_x4(aF[s ^ 1][mt], a_row[mt] + ((unit ^ a_sw[mt]) << 4));
            }
            const uint32_t brown = browbase + (uint32_t)(k16 + 1) * 8192u;
            ldsm_x4_t(bF[s ^ 1][0], brown + boff[0]);
            ldsm_x4_t(bF[s ^ 1][1], brown + boff[1]);
        }

        #pragma unroll
        for (int mt = 0; mt < 2; mt++) {
            mma_f16(acc[mt][4], aF[s][mt], bT[0][0], bT[0][1]);
            mma_f16(acc[mt][5], aF[s][mt], bT[0][2], bT[0][3]);
            mma_f16(acc[mt][6], aF[s][mt], bT[1][0], bT[1][1]);
            mma_f16(acc[mt][7], aF[s][mt], bT[1][2], bT[1][3]);
        }
    }
}

__global__ __launch_bounds__(512, 1)
void pair_mma_kernel(const float* __restrict__ b1,  const float* __restrict__ b2,
                     const float* __restrict__ b3,  const float* __restrict__ Wf,
                     const float* __restrict__ bfp, const float* __restrict__ bv1,
                     const float* __restrict__ Wv2, const float* __restrict__ bv2,
                     float* __restrict__ out)
{
    extern __shared__ char smraw[];
    const uint32_t smbase = smem_u32(smraw);
    const uint32_t abase  = (smbase + 1023u) & ~1023u;
    char* smp = smraw + (abase - smbase);
    float* qpb  = (float*)(smp + SM_VEC);
    float* vqb  = qpb + 256;
    float* b2s  = vqb + 256;
    float* b3s  = b2s + 256;
    float* wfs  = b3s + 256;
    float* wv2s = wfs + 256;
    float* red  = wv2s + 256;   // 512 floats: [row][warpN]
    float* vred = red + 512;    // 512 floats: [key][p]

    const int tid   = threadIdx.x;
    const int lane  = tid & 31;
    const int w     = tid >> 5;
    const int warpM = w & 3, warpN = w >> 2;
    const int quad  = tid >> 7;
    const int m     = tid & 127;
    const int bid = blockIdx.x;
    const int kt  = bid & 3;
    const int q   = (bid >> 2) & 511;
    const int b   = bid >> 11;
    const int k0  = kt << 7;
    const int rowb  = b * SKK + k0 + m;
    const int lbase = (b * SQ + q) * SKK + k0;

    // start the full W2 copy immediately (128KB, async)
    cp_layer((const char*)g_Wh, abase + SM_W, tid);

    // vectors
    {
        const int r = (b * SQ + q) * HH;
        if (tid < 256) {
            qpb[tid] = g_qp[r + tid] + b1[tid];
            b2s[tid] = b2[tid];
            wfs[tid] = Wf[tid];
        } else {
            int u = tid & 255;
            vqb[u]  = g_vq[r + u] + bv1[u];
            b3s[u]  = b3[u];
            wv2s[u] = Wv2[u];
        }
    }
    __syncthreads();

    // ---- build ALL of A (h0) + variance dot, overlapping the W2 copy ----
    {
        #pragma unroll 4
        for (int gg = 0; gg < 16; gg++) {
            int g0 = gg * 2;
            int j0 = 8 * g0 + quad * 2;
            float v0 = fmaxf(qpb[j0]     + g_kpT[j0 * MR + rowb],       0.f);
            float v1 = fmaxf(qpb[j0 + 1] + g_kpT[(j0 + 1) * MR + rowb], 0.f);
            float v2 = fmaxf(qpb[j0 + 8] + g_kpT[(j0 + 8) * MR + rowb], 0.f);
            float v3 = fmaxf(qpb[j0 + 9] + g_kpT[(j0 + 9) * MR + rowb], 0.f);
            a_store_units(smp, m, quad, g0, v0, v1, v2, v3);
        }
        float vacc = 0.f;
        #pragma unroll 8
        for (int jj = 0; jj < 64; jj++) {
            int j = quad * 64 + jj;
            vacc = fmaf(fmaxf(vqb[j] + g_vkT[j * MR + rowb], 0.f), wv2s[j], vacc);
        }
        vred[m * 4 + quad] = vacc;
    }
    asm volatile("cp.async.wait_group 0;" ::: "memory");
    __syncthreads();

    // ---- GEMM 1: D = h0 @ W2 (barrier-free) ----
    float acc[2][8][4];
    #pragma unroll
    for (int i = 0; i < 2; i++)
        #pragma unroll
        for (int j = 0; j < 8; j++)
            #pragma unroll
            for (int e = 0; e < 4; e++) acc[i][j][e] = 0.f;
    gemm_pass(abase, warpM, warpN, lane, acc);
    __syncthreads();   // all W2 + h0 reads done

    // start the full W3 copy (overlaps epilogue 1 + variance finalize)
    cp_layer((const char*)g_Wh + 131072, abase + SM_W, tid);

    // variance finalize
    if (tid < 128) {
        float s = vred[tid * 4] + vred[tid * 4 + 1] + vred[tid * 4 + 2] + vred[tid * 4 + 3]
                  + bv2[0];
        out[NTOT + lbase + tid] = softplusf(s);
    }

    // ---- epilogue 1: h1 = relu(D + b2) -> A buffer (fp16) ----
    {
        const int g  = lane >> 2;
        const int tg = lane & 3;
        #pragma unroll
        for (int mt = 0; mt < 2; mt++) {
            int r0 = warpM * 32 + mt * 16 + g;
            int r1 = r0 + 8;
            uint32_t row0 = (uint32_t)r0 * 512u;
            uint32_t row1 = (uint32_t)r1 * 512u;
            #pragma unroll
            for (int nt = 0; nt < 8; nt++) {
                int c0 = warpN * 64 + nt * 8 + tg * 2;
                float b20 = b2s[c0], b21 = b2s[c0 + 1];
                float v00 = fmaxf(acc[mt][nt][0] + b20, 0.f);
                float v01 = fmaxf(acc[mt][nt][1] + b21, 0.f);
                float v10 = fmaxf(acc[mt][nt][2] + b20, 0.f);
                float v11 = fmaxf(acc[mt][nt][3] + b21, 0.f);
                uint32_t unit = (uint32_t)(c0 >> 3);
                uint32_t o0 = row0 + ((unit ^ (uint32_t)(r0 & 7)) << 4) + (uint32_t)(tg * 4);
                uint32_t o1 = row1 + ((unit ^ (uint32_t)(r1 & 7)) << 4) + (uint32_t)(tg * 4);
                *(uint32_t*)(smp + SM_A + o0) = f16x2bits(v00, v01);
                *(uint32_t*)(smp + SM_A + o1) = f16x2bits(v10, v11);
            }
        }
    }
    asm volatile("cp.async.wait_group 0;" ::: "memory");
    __syncthreads();

    // ---- GEMM 2: D = h1 @ W3 (barrier-free) ----
    #pragma unroll
    for (int i = 0; i < 2; i++)
        #pragma unroll
        for (int j = 0; j < 8; j++)
            #pragma unroll
            for (int e = 0; e < 4; e++) acc[i][j][e] = 0.f;
    gemm_pass(abase, warpM, warpN, lane, acc);

    // ---- epilogue 2: logit = relu(D + b3) . Wf, cross-warp reduce ----
    {
        const int g  = lane >> 2;
        const int tg = lane & 3;
        #pragma unroll
        for (int mt = 0; mt < 2; mt++) {
            float lg0 = 0.f, lg1 = 0.f;
            #pragma unroll
            for (int nt = 0; nt < 8; nt++) {
                int c0 = warpN * 64 + nt * 8 + tg * 2;
                float b30 = b3s[c0], b31 = b3s[c0 + 1];
                float w0  = wfs[c0], w1  = wfs[c0 + 1];
                lg0 = fmaf(fmaxf(acc[mt][nt][0] + b30, 0.f), w0, lg0);
                lg0 = fmaf(fmaxf(acc[mt][nt][1] + b31, 0.f), w1, lg0);
                lg1 = fmaf(fmaxf(acc[mt][nt][2] + b30, 0.f), w0, lg1);
                lg1 = fmaf(fmaxf(acc[mt][nt][3] + b31, 0.f), w1, lg1);
            }
            lg0 += __shfl_xor_sync(0xffffffffu, lg0, 1);
            lg0 += __shfl_xor_sync(0xffffffffu, lg0, 2);
            lg1 += __shfl_xor_sync(0xffffffffu, lg1, 1);
            lg1 += __shfl_xor_sync(0xffffffffu, lg1, 2);
            if (tg == 0) {
                int r0 = warpM * 32 + mt * 16 + g;
                red[r0 * 4 + warpN]       = lg0;
                red[(r0 + 8) * 4 + warpN] = lg1;
            }
        }
    }
    __syncthreads();
    if (tid < 128) {
        float s = red[tid * 4] + red[tid * 4 + 1] + red[tid * 4 + 2] + red[tid * 4 + 3]
                  + bfp[0];
        out[lbase + tid] = s;
    }
}

// ---------------- launcher -----------------------------------------------------
extern "C" void kernel_launch(void* const* d_in, const int* in_sizes, int n_in,
                              void* d_out, int out_size)
{
    const float* query = (const float*)d_in[0];
    const float* key   = (const float*)d_in[1];
    const float* Wqe   = (const float*)d_in[2];
    const float* bqe   = (const float*)d_in[3];
    const float* Wke   = (const float*)d_in[4];
    const float* bke   = (const float*)d_in[5];
    const float* W1    = (const float*)d_in[6];
    const float* b1    = (const float*)d_in[7];
    const float* W2    = (const float*)d_in[8];
    const float* b2    = (const float*)d_in[9];
    const float* W3    = (const float*)d_in[10];
    const float* b3    = (const float*)d_in[11];
    const float* Wf    = (const float*)d_in[12];
    const float* bf    = (const float*)d_in[13];
    const float* Wv1   = (const float*)d_in[14];
    const float* bv1   = (const float*)d_in[15];
    const float* Wv2   = (const float*)d_in[16];
    const float* bv2   = (const float*)d_in[17];
    float* out = (float*)d_out;

    void *p_qf, *p_kf, *p_qp, *p_vq, *p_kpT, *p_vkT;
    cudaGetSymbolAddress(&p_qf,  g_qf);
    cudaGetSymbolAddress(&p_kf,  g_kf);
    cudaGetSymbolAddress(&p_qp,  g_qp);
    cudaGetSymbolAddress(&p_vq,  g_vq);
    cudaGetSymbolAddress(&p_kpT, g_kpT);
    cudaGetSymbolAddress(&p_vkT, g_vkT);

    // weight convert (independent of projections)
    wsplit_kernel<<<256, 256>>>(W2, W3);

    // encoders: qf = relu(query@Wqe+bqe), kf = relu(key@Wke+bke)
    ProjJob e0 { query, Wqe, bqe, (float*)p_qf, 0, 1, 0 };
    ProjJob e1 { key,   Wke, bke, (float*)p_kf, 0, 1, 0 };
    proj_batch_kernel<<<dim3(4, 32, 2), 256>>>(e0, e1, e0, e0, EE);

    // stage-2 projections
    ProjJob s0 { (const float*)p_qf, W1,  nullptr, (float*)p_qp,  0,   0, 0 };
    ProjJob s1 { (const float*)p_kf, W1,  nullptr, (float*)p_kpT, 256, 0, 1 };
    ProjJob s2 { (const float*)p_qf, Wv1, nullptr, (float*)p_vq,  0,   0, 0 };
    ProjJob s3 { (const float*)p_kf, Wv1, nullptr, (float*)p_vkT, 256, 0, 1 };
    proj_batch_kernel<<<dim3(4, 32, 4), 256>>>(s0, s1, s2, s3, HH);

    // main fused pairwise-MLP kernel (fp16 mma, barrier-free GEMMs)
    cudaFuncSetAttribute(pair_mma_kernel,
                         cudaFuncAttributeMaxDynamicSharedMemorySize, SMEM_BYTES);
    pair_mma_kernel<<<BB * SQ * (SKK / 128), 512, SMEM_BYTES>>>(
        b1, b2, b3, Wf, bf, bv1, Wv2, bv2, out);
}

// round 13
// speedup vs baseline: 2.4454x; 1.0637x over previous
#include <cuda_runtime.h>
#include <cuda_bf16.h>
#include <cuda_fp16.h>
#include <math.h>
#include <stdint.h>

// Problem dims (fixed)
#define BB   2
#define SQ   512
#define SKK  512
#define EE   512
#define HH   256
#define MR   1024            // B*SQ = B*SK
#define NTOT (BB*SQ*SKK)     // 524288

// ---------------- scratch (device globals; no allocation allowed) -------------
__device__ float g_qf [MR*HH];
__device__ float g_kf [MR*HH];
__device__ float g_qp [MR*HH];
__device__ float g_vq [MR*HH];
__device__ float g_kpT[HH*MR];   // [H][B*SK]
__device__ float g_vkT[HH*MR];   // [H][B*SK]
// fp16 weight images: word layout [layer][k][nw] (nw = n/2, f16x2)
__device__ __align__(16) uint32_t g_Wh[2 * 256 * 128];

// SMEM map (byte offsets from 1024-aligned base)  -- main kernel
#define SM_A   0u        // 128 rows x 512B  (fp16 A) = 64KB
#define SM_W   65536u    // 256 rows x 512B  (full weight layer, fp16) = 128KB
#define SM_VEC 196608u
#define SMEM_BYTES (206848 + 1024)

// ---------------- PTX helpers --------------------------------------------------
__device__ __forceinline__ uint32_t smem_u32(const void* p) {
    return (uint32_t)__cvta_generic_to_shared(p);
}
__device__ __forceinline__ void ldsm_x4(uint32_t (&r)[4], uint32_t addr) {
    asm volatile("ldmatrix.sync.aligned.m8n8.x4.shared.b16 {%0,%1,%2,%3}, [%4];"
        : "=r"(r[0]), "=r"(r[1]), "=r"(r[2]), "=r"(r[3]) : "r"(addr));
}
__device__ __forceinline__ void ldsm_x4_t(uint32_t (&r)[4], uint32_t addr) {
    asm volatile("ldmatrix.sync.aligned.m8n8.x4.trans.shared.b16 {%0,%1,%2,%3}, [%4];"
        : "=r"(r[0]), "=r"(r[1]), "=r"(r[2]), "=r"(r[3]) : "r"(addr));
}
__device__ __forceinline__ void mma_f16(float (&d)[4], const uint32_t (&a)[4],
                                        uint32_t b0, uint32_t b1) {
    asm volatile("mma.sync.aligned.m16n8k16.row.col.f32.f16.f16.f32 "
        "{%0,%1,%2,%3}, {%4,%5,%6,%7}, {%8,%9}, {%0,%1,%2,%3};"
        : "+f"(d[0]), "+f"(d[1]), "+f"(d[2]), "+f"(d[3])
        : "r"(a[0]), "r"(a[1]), "r"(a[2]), "r"(a[3]), "r"(b0), "r"(b1));
}
__device__ __forceinline__ unsigned long long pack_dup(float a) {
    unsigned long long r;
    asm("mov.b64 %0, {%1, %1};" : "=l"(r) : "f"(a));
    return r;
}
__device__ __forceinline__ void unpack2(unsigned long long v, float& lo, float& hi) {
    asm("mov.b64 {%0, %1}, %2;" : "=f"(lo), "=f"(hi) : "l"(v));
}
__device__ __forceinline__ void ffma2(unsigned long long& acc, unsigned long long a,
                                      unsigned long long b) {
    asm("fma.rn.f32x2 %0, %1, %2, %0;" : "+l"(acc) : "l"(a), "l"(b));
}

// ---------------- small math helpers ------------------------------------------
__device__ __forceinline__ uint32_t f16x2bits(float v0, float v1) {
    __half2 h = __floats2half2_rn(v0, v1);
    return *reinterpret_cast<uint32_t*>(&h);
}
__device__ __forceinline__ float softplusf(float x) {
    if (x > 20.f) return x;
    return log1pf(expf(x));
}

// ---------------- weight convert prologue (fp16) -------------------------------
__global__ __launch_bounds__(256)
void wsplit_kernel(const float* __restrict__ W2, const float* __restrict__ W3)
{
    int idx = blockIdx.x * 256 + threadIdx.x;     // 0..65535
    int layer = idx >> 15;
    int rem   = idx & 32767;
    int k  = rem >> 7;          // 0..255
    int nw = rem & 127;         // 0..127
    const float* W = layer ? W3 : W2;
    float v0 = W[k * 256 + nw * 2];
    float v1 = W[k * 256 + nw * 2 + 1];
    g_Wh[idx] = f16x2bits(v0, v1);
}

// ---------------- prologue: batched 1024x256 projection GEMM -------------------
// cp.async double-buffered A/W chunk staging; one barrier per K-chunk.
struct ProjJob {
    const float* A; const float* W; const float* bias; float* C;
    int wrow0; int doRelu; int doTrans;
};

#define PAS_LD 20   // As row stride (floats): 16 data + 4 pad (80B, 16B-aligned)

__device__ __forceinline__ void proj_stage_chunk(const float* __restrict__ A,
                                                 const float* __restrict__ W,
                                                 int K, int wrow0, int m0, int n0,
                                                 int kc, uint32_t asb, uint32_t wsb,
                                                 int tid)
{
    if (tid < 128) {
        int m = tid >> 2, seg = tid & 3;
        const float* src = A + (m0 + m) * K + kc + seg * 4;
        uint32_t dst = asb + (uint32_t)(m * PAS_LD + seg * 4) * 4u;
        asm volatile("cp.async.cg.shared.global [%0], [%1], 16;"
                     :: "r"(dst), "l"(src));
    }
    {
        int kk = tid >> 4, seg = tid & 15;
        const float* src = W + (wrow0 + kc + kk) * 256 + n0 + seg * 4;
        uint32_t dst = wsb + (uint32_t)(kk * 64 + seg * 4) * 4u;
        asm volatile("cp.async.cg.shared.global [%0], [%1], 16;"
                     :: "r"(dst), "l"(src));
    }
    asm volatile("cp.async.commit_group;" ::: "memory");
}

__global__ __launch_bounds__(256)
void proj_batch_kernel(ProjJob j0, ProjJob j1, ProjJob j2, ProjJob j3, int K)
{
    ProjJob jb = (blockIdx.z == 0) ? j0 : (blockIdx.z == 1) ? j1 :
                 (blockIdx.z == 2) ? j2 : j3;
    __shared__ __align__(16) float As[2][32 * PAS_LD];
    __shared__ __align__(16) float Ws[2][16 * 64];
    const int tid = threadIdx.x;
    const int m0  = blockIdx.y * 32;
    const int n0  = blockIdx.x * 64;
    const int ty  = tid >> 4, tx = tid & 15;

    const uint32_t asb0 = smem_u32(&As[0][0]), asb1 = smem_u32(&As[1][0]);
    const uint32_t wsb0 = smem_u32(&Ws[0][0]), wsb1 = smem_u32(&Ws[1][0]);

    unsigned long long acc2[2][2] = {{0ull, 0ull}, {0ull, 0ull}};
    const int nch = K >> 4;

    proj_stage_chunk(jb.A, jb.W, K, jb.wrow0, m0, n0, 0, asb0, wsb0, tid);

    for (int ch = 0; ch < nch; ch++) {
        if (ch + 1 < nch)
            proj_stage_chunk(jb.A, jb.W, K, jb.wrow0, m0, n0, (ch + 1) << 4,
                             (ch & 1) ? asb0 : asb1, (ch & 1) ? wsb0 : wsb1, tid);
        if (ch + 1 < nch) { asm volatile("cp.async.wait_group 1;" ::: "memory"); }
        else              { asm volatile("cp.async.wait_group 0;" ::: "memory"); }
        __syncthreads();

        const float* Ab = As[ch & 1];
        const float* Wb = Ws[ch & 1];
        #pragma unroll
        for (int kk = 0; kk < 16; kk++) {
            unsigned long long a0d = pack_dup(Ab[(ty * 2) * PAS_LD + kk]);
            unsigned long long a1d = pack_dup(Ab[(ty * 2 + 1) * PAS_LD + kk]);
            unsigned long long w01 = *(const unsigned long long*)&Wb[kk * 64 + tx * 4];
            unsigned long long w23 = *(const unsigned long long*)&Wb[kk * 64 + tx * 4 + 2];
            ffma2(acc2[0][0], a0d, w01);
            ffma2(acc2[0][1], a0d, w23);
            ffma2(acc2[1][0], a1d, w01);
            ffma2(acc2[1][1], a1d, w23);
        }
        __syncthreads();
    }
    #pragma unroll
    for (int i = 0; i < 2; i++) {
        float vout[4];
        unpack2(acc2[i][0], vout[0], vout[1]);
        unpack2(acc2[i][1], vout[2], vout[3]);
        const int r = m0 + ty * 2 + i;
        #pragma unroll
        for (int j = 0; j < 4; j++) {
            const int n = n0 + tx * 4 + j;
            float v = vout[j] + (jb.bias ? jb.bias[n] : 0.f);
            if (jb.doRelu) v = fmaxf(v, 0.f);
            if (jb.doTrans) jb.C[n * MR + r] = v;
            else            jb.C[r * 256 + n] = v;
        }
    }
}

// ---------------- main pairwise-MLP kernel (fp16 mma, interleaved A-build) -----

// copy one full weight layer (128KB, 256 rows x 512B) into SM_W with swizzle
__device__ __forceinline__ void cp_layer(const char* __restrict__ src,
                                         uint32_t dstbase, int tid)
{
    #pragma unroll
    for (int i = 0; i < 16; i++) {
        int e = tid + i * 512;                 // 0..8191
        int k = e >> 5, u = e & 31;            // row (0..255), 16B unit
        uint32_t d = dstbase + (uint32_t)k * 512u + (uint32_t)((u ^ (k & 7)) << 4);
        asm volatile("cp.async.cg.shared.global [%0], [%1], 16;"
                     :: "r"(d), "l"(src + e * 16));
    }
    asm volatile("cp.async.commit_group;" ::: "memory");
}

// build 2 adjacent 16B units (g0, g0+1) of one A row: j0 = 8*g0 + quad*2
__device__ __forceinline__ void a_store_units(char* smp, int m, int quad, int g0,
                                              float v0, float v1, float v2, float v3)
{
    char* arow = smp + (uint32_t)m * 512u;
    uint32_t off0 = (uint32_t)(((g0 ^ (m & 7)) << 4) + quad * 4);
    *(uint32_t*)(arow + SM_A + off0) = f16x2bits(v0, v1);
    uint32_t off1 = (uint32_t)((((g0 + 1) ^ (m & 7)) << 4) + quad * 4);
    *(uint32_t*)(arow + SM_A + off1) = f16x2bits(v2, v3);
}

// Half of a 128x256x256 fp16 GEMM: 8 k16 steps starting at k16_0 (0 or 8).
// BUILD: builds A slice k16 = i+8 during iteration i (valid only for k16_0=0,
//        with a __syncthreads between the two halves).
// VAR:   accumulates 4 variance-dot terms per iteration, j = quad*64+vbase+i*4.
template<bool BUILD, bool VAR>
__device__ __forceinline__ void gemm_half(uint32_t abase, int k16_0,
                                          int warpM, int warpN, int lane,
                                          float (&acc)[2][8][4],
                                          char* smp, const float* __restrict__ qpb,
                                          const float* __restrict__ vqb,
                                          const float* __restrict__ wv2s,
                                          int rowb, float& vacc,
                                          int quad, int m, int vbase)
{
    const int rit  = (lane & 7) | (((lane >> 3) & 1) << 3); // row within 16-tile
    const int koff = lane >> 4;                              // 0/1: unit select
    uint32_t a_row[2]; uint32_t a_sw[2];
    #pragma unroll
    for (int mt = 0; mt < 2; mt++) {
        int rr = warpM * 32 + mt * 16 + rit;
        a_row[mt] = abase + (uint32_t)rr * 512u;
        a_sw[mt]  = (uint32_t)(rr & 7);
    }
    const uint32_t ksw = (uint32_t)(rit & 7);
    uint32_t boff[4];
    #pragma unroll
    for (int np = 0; np < 4; np++) {
        uint32_t nunit = (uint32_t)(warpN * 8 + np * 2 + koff);
        boff[np] = ((nunit ^ ksw) << 4);
    }
    const uint32_t browbase = abase + SM_W + (uint32_t)rit * 512u;

    // fragment double buffers: parity = i & 1 (k16_0 is even)
    uint32_t aF[2][2][4];
    uint32_t bF[2][2][4];
    #pragma unroll
    for (int mt = 0; mt < 2; mt++)
        ldsm_x4(aF[0][mt],
                a_row[mt] + (((uint32_t)(k16_0 * 2 + koff) ^ a_sw[mt]) << 4));
    {
        const uint32_t br0 = browbase + (uint32_t)k16_0 * 8192u;
        ldsm_x4_t(bF[0][0], br0 + boff[0]);
        ldsm_x4_t(bF[0][1], br0 + boff[1]);
    }

    #pragma unroll
    for (int i = 0; i < 8; i++) {
        const int k16 = k16_0 + i;
        const int s = i & 1;

        // ---- early global loads (latency hidden behind MMAs) ----
        float kp0, kp1, kp2, kp3;
        float vk0, vk1, vk2, vk3;
        int j0 = 0, jv = 0;
        if (BUILD) {
            int g0 = 2 * (i + 8);
            j0 = 8 * g0 + quad * 2;
            kp0 = g_kpT[j0 * MR + rowb];
            kp1 = g_kpT[(j0 + 1) * MR + rowb];
            kp2 = g_kpT[(j0 + 8) * MR + rowb];
            kp3 = g_kpT[(j0 + 9) * MR + rowb];
        }
        if (VAR) {
            jv = quad * 64 + vbase + i * 4;
            vk0 = g_vkT[jv * MR + rowb];
            vk1 = g_vkT[(jv + 1) * MR + rowb];
            vk2 = g_vkT[(jv + 2) * MR + rowb];
            vk3 = g_vkT[(jv + 3) * MR + rowb];
        }

        // ---- B np=2,3 for current k16 ----
        uint32_t bT[2][4];
        const uint32_t brow = browbase + (uint32_t)k16 * 8192u;
        ldsm_x4_t(bT[0], brow + boff[2]);
        ldsm_x4_t(bT[1], brow + boff[3]);

        // ---- MMA np=0,1 with pre-loaded fragments ----
        #pragma unroll
        for (int mt = 0; mt < 2; mt++) {
            mma_f16(acc[mt][0], aF[s][mt], bF[s][0][0], bF[s][0][1]);
            mma_f16(acc[mt][1], aF[s][mt], bF[s][0][2], bF[s][0][3]);
            mma_f16(acc[mt][2], aF[s][mt], bF[s][1][0], bF[s][1][1]);
            mma_f16(acc[mt][3], aF[s][mt], bF[s][1][2], bF[s][1][3]);
        }

        // ---- prefetch fragments for k16+1 (within this half only) ----
        if (i < 7) {
            #pragma unroll
            for (int mt = 0; mt < 2; mt++) {
                uint32_t unit = (uint32_t)((k16 + 1) * 2 + koff);
                ldsm_x4(aF[s ^ 1][mt], a_row[mt] + ((unit ^ a_sw[mt]) << 4));
            }
            const uint32_t brown = browbase + (uint32_t)(k16 + 1) * 8192u;
            ldsm_x4_t(bF[s ^ 1][0], brown + boff[0]);
            ldsm_x4_t(bF[s ^ 1][1], brown + boff[1]);
        }

        // ---- MMA np=2,3 ----
        #pragma unroll
        for (int mt = 0; mt < 2; mt++) {
            mma_f16(acc[mt][4], aF[s][mt], bT[0][0], bT[0][1]);
            mma_f16(acc[mt][5], aF[s][mt], bT[0][2], bT[0][3]);
            mma_f16(acc[mt][6], aF[s][mt], bT[1][0], bT[1][1]);
            mma_f16(acc[mt][7], aF[s][mt], bT[1][2], bT[1][3]);
        }

        // ---- late: A-build stores + variance FMAs ----
        if (BUILD) {
            int g0 = 2 * (i + 8);
            float v0 = fmaxf(qpb[j0]     + kp0, 0.f);
            float v1 = fmaxf(qpb[j0 + 1] + kp1, 0.f);
            float v2 = fmaxf(qpb[j0 + 8] + kp2, 0.f);
            float v3 = fmaxf(qpb[j0 + 9] + kp3, 0.f);
            a_store_units(smp, m, quad, g0, v0, v1, v2, v3);
        }
        if (VAR) {
            vacc = fmaf(fmaxf(vqb[jv]     + vk0, 0.f), wv2s[jv],     vacc);
            vacc = fmaf(fmaxf(vqb[jv + 1] + vk1, 0.f), wv2s[jv + 1], vacc);
            vacc = fmaf(fmaxf(vqb[jv + 2] + vk2, 0.f), wv2s[jv + 2], vacc);
            vacc = fmaf(fmaxf(vqb[jv + 3] + vk3, 0.f), wv2s[jv + 3], vacc);
        }
    }
}

__global__ __launch_bounds__(512, 1)
void pair_mma_kernel(const float* __restrict__ b1,  const float* __restrict__ b2,
                     const float* __restrict__ b3,  const float* __restrict__ Wf,
                     const float* __restrict__ bfp, const float* __restrict__ bv1,
                     const float* __restrict__ Wv2, const float* __restrict__ bv2,
                     float* __restrict__ out)
{
    extern __shared__ char smraw[];
    const uint32_t smbase = smem_u32(smraw);
    const uint32_t abase  = (smbase + 1023u) & ~1023u;
    char* smp = smraw + (abase - smbase);
    float* qpb  = (float*)(smp + SM_VEC);
    float* vqb  = qpb + 256;
    float* b2s  = vqb + 256;
    float* b3s  = b2s + 256;
    float* wfs  = b3s + 256;
    float* wv2s = wfs + 256;
    float* red  = wv2s + 256;   // 512 floats: [row][warpN]
    float* vred = red + 512;    // 512 floats: [key][p]

    const int tid   = threadIdx.x;
    const int lane  = tid & 31;
    const int w     = tid >> 5;
    const int warpM = w & 3, warpN = w >> 2;
    const int quad  = tid >> 7;
    const int m     = tid & 127;
    const int bid = blockIdx.x;
    const int kt  = bid & 3;
    const int q   = (bid >> 2) & 511;
    const int b   = bid >> 11;
    const int k0  = kt << 7;
    const int rowb  = b * SKK + k0 + m;
    const int lbase = (b * SQ + q) * SKK + k0;

    // start the full W2 copy immediately (128KB, async)
    cp_layer((const char*)g_Wh, abase + SM_W, tid);

    // vectors
    {
        const int r = (b * SQ + q) * HH;
        if (tid < 256) {
            qpb[tid] = g_qp[r + tid] + b1[tid];
            b2s[tid] = b2[tid];
            wfs[tid] = Wf[tid];
        } else {
            int u = tid & 255;
            vqb[u]  = g_vq[r + u] + bv1[u];
            b3s[u]  = b3[u];
            wv2s[u] = Wv2[u];
        }
    }
    __syncthreads();

    // ---- prebuild A slices k16 0..7 only (units 0..15), overlapping W2 copy ----
    {
        #pragma unroll 4
        for (int gg = 0; gg < 8; gg++) {
            int g0 = gg * 2;
            int j0 = 8 * g0 + quad * 2;
            float v0 = fmaxf(qpb[j0]     + g_kpT[j0 * MR + rowb],       0.f);
            float v1 = fmaxf(qpb[j0 + 1] + g_kpT[(j0 + 1) * MR + rowb], 0.f);
            float v2 = fmaxf(qpb[j0 + 8] + g_kpT[(j0 + 8) * MR + rowb], 0.f);
            float v3 = fmaxf(qpb[j0 + 9] + g_kpT[(j0 + 9) * MR + rowb], 0.f);
            a_store_units(smp, m, quad, g0, v0, v1, v2, v3);
        }
    }
    asm volatile("cp.async.wait_group 0;" ::: "memory");
    __syncthreads();

    // ---- GEMM 1: D = h0 @ W2 ----
    // first half (k16 0..7): builds A k16 8..15 + variance j 0..31 (per quad)
    float acc[2][8][4];
    #pragma unroll
    for (int i = 0; i < 2; i++)
        #pragma unroll
        for (int j = 0; j < 8; j++)
            #pragma unroll
            for (int e = 0; e < 4; e++) acc[i][j][e] = 0.f;
    float vacc = 0.f;
    gemm_half<true, true>(abase, 0, warpM, warpN, lane, acc,
                          smp, qpb, vqb, wv2s, rowb, vacc, quad, m, 0);
    __syncthreads();   // A k16 8..15 visible to all warps
    // second half (k16 8..15): variance j 32..63 (per quad)
    gemm_half<false, true>(abase, 8, warpM, warpN, lane, acc,
                           smp, qpb, vqb, wv2s, rowb, vacc, quad, m, 32);
    vred[m * 4 + quad] = vacc;
    __syncthreads();   // all W2 + h0 reads done; vred complete

    // start the full W3 copy (overlaps epilogue 1 + variance finalize)
    cp_layer((const char*)g_Wh + 131072, abase + SM_W, tid);

    // variance finalize
    if (tid < 128) {
        float s = vred[tid * 4] + vred[tid * 4 + 1] + vred[tid * 4 + 2] + vred[tid * 4 + 3]
                  + bv2[0];
        out[NTOT + lbase + tid] = softplusf(s);
    }

    // ---- epilogue 1: h1 = relu(D + b2) -> A buffer (fp16) ----
    {
        const int g  = lane >> 2;
        const int tg = lane & 3;
        #pragma unroll
        for (int mt = 0; mt < 2; mt++) {
            int r0 = warpM * 32 + mt * 16 + g;
            int r1 = r0 + 8;
            uint32_t row0 = (uint32_t)r0 * 512u;
            uint32_t row1 = (uint32_t)r1 * 512u;
            #pragma unroll
            for (int nt = 0; nt < 8; nt++) {
                int c0 = warpN * 64 + nt * 8 + tg * 2;
                float b20 = b2s[c0], b21 = b2s[c0 + 1];
                float v00 = fmaxf(acc[mt][nt][0] + b20, 0.f);
                float v01 = fmaxf(acc[mt][nt][1] + b21, 0.f);
                float v10 = fmaxf(acc[mt][nt][2] + b20, 0.f);
                float v11 = fmaxf(acc[mt][nt][3] + b21, 0.f);
                uint32_t unit = (uint32_t)(c0 >> 3);
                uint32_t o0 = row0 + ((unit ^ (uint32_t)(r0 & 7)) << 4) + (uint32_t)(tg * 4);
                uint32_t o1 = row1 + ((unit ^ (uint32_t)(r1 & 7)) << 4) + (uint32_t)(tg * 4);
                *(uint32_t*)(smp + SM_A + o0) = f16x2bits(v00, v01);
                *(uint32_t*)(smp + SM_A + o1) = f16x2bits(v10, v11);
            }
        }
    }
    asm volatile("cp.async.wait_group 0;" ::: "memory");
    __syncthreads();

    // ---- GEMM 2: D = h1 @ W3 (barrier-free, two plain halves) ----
    #pragma unroll
    for (int i = 0; i < 2; i++)
        #pragma unroll
        for (int j = 0; j < 8; j++)
            #pragma unroll
            for (int e = 0; e < 4; e++) acc[i][j][e] = 0.f;
    gemm_half<false, false>(abase, 0, warpM, warpN, lane, acc,
                            smp, qpb, vqb, wv2s, rowb, vacc, quad, m, 0);
    gemm_half<false, false>(abase, 8, warpM, warpN, lane, acc,
                            smp, qpb, vqb, wv2s, rowb, vacc, quad, m, 0);

    // ---- epilogue 2: logit = relu(D + b3) . Wf, cross-warp reduce ----
    {
        const int g  = lane >> 2;
        const int tg = lane & 3;
        #pragma unroll
        for (int mt = 0; mt < 2; mt++) {
            float lg0 = 0.f, lg1 = 0.f;
            #pragma unroll
            for (int nt = 0; nt < 8; nt++) {
                int c0 = warpN * 64 + nt * 8 + tg * 2;
                float b30 = b3s[c0], b31 = b3s[c0 + 1];
                float w0  = wfs[c0], w1  = wfs[c0 + 1];
                lg0 = fmaf(fmaxf(acc[mt][nt][0] + b30, 0.f), w0, lg0);
                lg0 = fmaf(fmaxf(acc[mt][nt][1] + b31, 0.f), w1, lg0);
                lg1 = fmaf(fmaxf(acc[mt][nt][2] + b30, 0.f), w0, lg1);
                lg1 = fmaf(fmaxf(acc[mt][nt][3] + b31, 0.f), w1, lg1);
            }
            lg0 += __shfl_xor_sync(0xffffffffu, lg0, 1);
            lg0 += __shfl_xor_sync(0xffffffffu, lg0, 2);
            lg1 += __shfl_xor_sync(0xffffffffu, lg1, 1);
            lg1 += __shfl_xor_sync(0xffffffffu, lg1, 2);
            if (tg == 0) {
                int r0 = warpM * 32 + mt * 16 + g;
                red[r0 * 4 + warpN]       = lg0;
                red[(r0 + 8) * 4 + warpN] = lg1;
            }
        }
    }
    __syncthreads();
    if (tid < 128) {
        float s = red[tid * 4] + red[tid * 4 + 1] + red[tid * 4 + 2] + red[tid * 4 + 3]
                  + bfp[0];
        out[lbase + tid] = s;
    }
}

// ---------------- launcher -----------------------------------------------------
extern "C" void kernel_launch(void* const* d_in, const int* in_sizes, int n_in,
                              void* d_out, int out_size)
{
    const float* query = (const float*)d_in[0];
    const float* key   = (const float*)d_in[1];
    const float* Wqe   = (const float*)d_in[2];
    const float* bqe   = (const float*)d_in[3];
    const float* Wke   = (const float*)d_in[4];
    const float* bke   = (const float*)d_in[5];
    const float* W1    = (const float*)d_in[6];
    const float* b1    = (const float*)d_in[7];
    const float* W2    = (const float*)d_in[8];
    const float* b2    = (const float*)d_in[9];
    const float* W3    = (const float*)d_in[10];
    const float* b3    = (const float*)d_in[11];
    const float* Wf    = (const float*)d_in[12];
    const float* bf    = (const float*)d_in[13];
    const float* Wv1   = (const float*)d_in[14];
    const float* bv1   = (const float*)d_in[15];
    const float* Wv2   = (const float*)d_in[16];
    const float* bv2   = (const float*)d_in[17];
    float* out = (float*)d_out;

    void *p_qf, *p_kf, *p_qp, *p_vq, *p_kpT, *p_vkT;
    cudaGetSymbolAddress(&p_qf,  g_qf);
    cudaGetSymbolAddress(&p_kf,  g_kf);
    cudaGetSymbolAddress(&p_qp,  g_qp);
    cudaGetSymbolAddress(&p_vq,  g_vq);
    cudaGetSymbolAddress(&p_kpT, g_kpT);
    cudaGetSymbolAddress(&p_vkT, g_vkT);

    // weight convert (independent of projections)
    wsplit_kernel<<<256, 256>>>(W2, W3);

    // encoders: qf = relu(query@Wqe+bqe), kf = relu(key@Wke+bke)
    ProjJob e0 { query, Wqe, bqe, (float*)p_qf, 0, 1, 0 };
    ProjJob e1 { key,   Wke, bke, (float*)p_kf, 0, 1, 0 };
    proj_batch_kernel<<<dim3(4, 32, 2), 256>>>(e0, e1, e0, e0, EE);

    // stage-2 projections
    ProjJob s0 { (const float*)p_qf, W1,  nullptr, (float*)p_qp,  0,   0, 0 };
    ProjJob s1 { (const float*)p_kf, W1,  nullptr, (float*)p_kpT, 256, 0, 1 };
    ProjJob s2 { (const float*)p_qf, Wv1, nullptr, (float*)p_vq,  0,   0, 0 };
    ProjJob s3 { (const float*)p_kf, Wv1, nullptr, (float*)p_vkT, 256, 0, 1 };
    proj_batch_kernel<<<dim3(4, 32, 4), 256>>>(s0, s1, s2, s3, HH);

    // main fused pairwise-MLP kernel (fp16 mma, interleaved A-build/variance)
    cudaFuncSetAttribute(pair_mma_kernel,
                         cudaFuncAttributeMaxDynamicSharedMemorySize, SMEM_BYTES);
    pair_mma_kernel<<<BB * SQ * (SKK / 128), 512, SMEM_BYTES>>>(
        b1, b2, b3, Wf, bf, bv1, Wv2, bv2, out);
}

// round 14
// speedup vs baseline: 2.5227x; 1.0316x over previous
#include <cuda_runtime.h>
#include <cuda_bf16.h>
#include <cuda_fp16.h>
#include <math.h>
#include <stdint.h>

// Problem dims (fixed)
#define BB   2
#define SQ   512
#define SKK  512
#define EE   512
#define HH   256
#define MR   1024            // B*SQ = B*SK
#define NTOT (BB*SQ*SKK)     // 524288

// ---------------- scratch (device globals; no allocation allowed) -------------
__device__ float g_qf [MR*HH];
__device__ float g_kf [MR*HH];
__device__ float g_qp [MR*HH];
__device__ float g_vq [MR*HH];
__device__ float g_kpT[HH*MR];   // [H][B*SK]
__device__ float g_vkT[HH*MR];   // [H][B*SK]
// fp16 weight images: word layout [layer][k][nw] (nw = n/2, f16x2)
__device__ __align__(16) uint32_t g_Wh[2 * 256 * 128];

// SMEM map (byte offsets from 1024-aligned base)  -- main kernel
#define SM_A   0u        // 128 rows x 512B  (fp16 A) = 64KB
#define SM_W   65536u    // 256 rows x 512B  (full weight layer, fp16) = 128KB
#define SM_VEC 196608u
#define SMEM_BYTES (206848 + 1024)

// ---------------- PTX helpers --------------------------------------------------
__device__ __forceinline__ uint32_t smem_u32(const void* p) {
    return (uint32_t)__cvta_generic_to_shared(p);
}
__device__ __forceinline__ void ldsm_x4(uint32_t (&r)[4], uint32_t addr) {
    asm volatile("ldmatrix.sync.aligned.m8n8.x4.shared.b16 {%0,%1,%2,%3}, [%4];"
        : "=r"(r[0]), "=r"(r[1]), "=r"(r[2]), "=r"(r[3]) : "r"(addr));
}
__device__ __forceinline__ void ldsm_x4_t(uint32_t (&r)[4], uint32_t addr) {
    asm volatile("ldmatrix.sync.aligned.m8n8.x4.trans.shared.b16 {%0,%1,%2,%3}, [%4];"
        : "=r"(r[0]), "=r"(r[1]), "=r"(r[2]), "=r"(r[3]) : "r"(addr));
}
__device__ __forceinline__ void mma_f16(float (&d)[4], const uint32_t (&a)[4],
                                        uint32_t b0, uint32_t b1) {
    asm volatile("mma.sync.aligned.m16n8k16.row.col.f32.f16.f16.f32 "
        "{%0,%1,%2,%3}, {%4,%5,%6,%7}, {%8,%9}, {%0,%1,%2,%3};"
        : "+f"(d[0]), "+f"(d[1]), "+f"(d[2]), "+f"(d[3])
        : "r"(a[0]), "r"(a[1]), "r"(a[2]), "r"(a[3]), "r"(b0), "r"(b1));
}
__device__ __forceinline__ unsigned long long pack_dup(float a) {
    unsigned long long r;
    asm("mov.b64 %0, {%1, %1};" : "=l"(r) : "f"(a));
    return r;
}
__device__ __forceinline__ void unpack2(unsigned long long v, float& lo, float& hi) {
    asm("mov.b64 {%0, %1}, %2;" : "=f"(lo), "=f"(hi) : "l"(v));
}
__device__ __forceinline__ void ffma2(unsigned long long& acc, unsigned long long a,
                                      unsigned long long b) {
    asm("fma.rn.f32x2 %0, %1, %2, %0;" : "+l"(acc) : "l"(a), "l"(b));
}

// ---------------- small math helpers ------------------------------------------
__device__ __forceinline__ uint32_t f16x2bits(float v0, float v1) {
    __half2 h = __floats2half2_rn(v0, v1);
    return *reinterpret_cast<uint32_t*>(&h);
}
__device__ __forceinline__ float softplusf(float x) {
    if (x > 20.f) return x;
    return log1pf(expf(x));
}

// ---------------- prologue: batched 1024x256 projection GEMM (64x64 tiles) -----
// cp.async double-buffered A/W chunk staging; one barrier per K-chunk.
// blockIdx.z == wsplitZ runs the weight-convert instead (merged launch).
struct ProjJob {
    const float* A; const float* W; const float* bias; float* C;
    int wrow0; int doRelu; int doTrans;
};

#define PAS_LD 20   // As row stride (floats): 16 data + 4 pad

__device__ __forceinline__ void proj_stage_chunk(const float* __restrict__ A,
                                                 const float* __restrict__ W,
                                                 int K, int wrow0, int m0, int n0,
                                                 int kc, uint32_t asb, uint32_t wsb,
                                                 int tid)
{
    // A chunk: 64 rows x 16 k floats; 1 x 16B per thread
    {
        int m = tid >> 2, seg = tid & 3;
        const float* src = A + (m0 + m) * K + kc + seg * 4;
        uint32_t dst = asb + (uint32_t)(m * PAS_LD + seg * 4) * 4u;
        asm volatile("cp.async.cg.shared.global [%0], [%1], 16;"
                     :: "r"(dst), "l"(src));
    }
    // W chunk: 16 k-rows x 64 n floats; 1 x 16B per thread
    {
        int kk = tid >> 4, seg = tid & 15;
        const float* src = W + (wrow0 + kc + kk) * 256 + n0 + seg * 4;
        uint32_t dst = wsb + (uint32_t)(kk * 64 + seg * 4) * 4u;
        asm volatile("cp.async.cg.shared.global [%0], [%1], 16;"
                     :: "r"(dst), "l"(src));
    }
    asm volatile("cp.async.commit_group;" ::: "memory");
}

__global__ __launch_bounds__(256)
void proj_batch_kernel(ProjJob j0, ProjJob j1, ProjJob j2, ProjJob j3, int K,
                       const float* __restrict__ Wc2,
                       const float* __restrict__ Wc3, int wsplitZ)
{
    const int tid = threadIdx.x;
    if ((int)blockIdx.z == wsplitZ) {
        // weight convert: 65536 items over 64 blocks x 256 threads x 4
        int base = (blockIdx.y * gridDim.x + blockIdx.x) * 256 + tid;
        #pragma unroll
        for (int i = 0; i < 4; i++) {
            int idx = base + i * 16384;
            int layer = idx >> 15;
            int rem   = idx & 32767;
            int k  = rem >> 7;
            int nw = rem & 127;
            const float* W = layer ? Wc3 : Wc2;
            g_Wh[idx] = f16x2bits(W[k * 256 + nw * 2], W[k * 256 + nw * 2 + 1]);
        }
        return;
    }
    ProjJob jb = (blockIdx.z == 0) ? j0 : (blockIdx.z == 1) ? j1 :
                 (blockIdx.z == 2) ? j2 : j3;
    __shared__ __align__(16) float As[2][64 * PAS_LD];
    __shared__ __align__(16) float Ws[2][16 * 64];
    const int m0  = blockIdx.y * 64;
    const int n0  = blockIdx.x * 64;
    const int ty  = tid >> 4, tx = tid & 15;

    const uint32_t asb0 = smem_u32(&As[0][0]), asb1 = smem_u32(&As[1][0]);
    const uint32_t wsb0 = smem_u32(&Ws[0][0]), wsb1 = smem_u32(&Ws[1][0]);

    unsigned long long acc2[4][2] = {};
    const int nch = K >> 4;

    proj_stage_chunk(jb.A, jb.W, K, jb.wrow0, m0, n0, 0, asb0, wsb0, tid);

    for (int ch = 0; ch < nch; ch++) {
        if (ch + 1 < nch)
            proj_stage_chunk(jb.A, jb.W, K, jb.wrow0, m0, n0, (ch + 1) << 4,
                             (ch & 1) ? asb0 : asb1, (ch & 1) ? wsb0 : wsb1, tid);
        if (ch + 1 < nch) { asm volatile("cp.async.wait_group 1;" ::: "memory"); }
        else              { asm volatile("cp.async.wait_group 0;" ::: "memory"); }
        __syncthreads();

        const float* Ab = As[ch & 1];
        const float* Wb = Ws[ch & 1];
        #pragma unroll
        for (int kk = 0; kk < 16; kk++) {
            unsigned long long w01 = *(const unsigned long long*)&Wb[kk * 64 + tx * 4];
            unsigned long long w23 = *(const unsigned long long*)&Wb[kk * 64 + tx * 4 + 2];
            #pragma unroll
            for (int i = 0; i < 4; i++) {
                unsigned long long ad = pack_dup(Ab[(ty * 4 + i) * PAS_LD + kk]);
                ffma2(acc2[i][0], ad, w01);
                ffma2(acc2[i][1], ad, w23);
            }
        }
        __syncthreads();
    }
    #pragma unroll
    for (int i = 0; i < 4; i++) {
        float vout[4];
        unpack2(acc2[i][0], vout[0], vout[1]);
        unpack2(acc2[i][1], vout[2], vout[3]);
        const int r = m0 + ty * 4 + i;
        #pragma unroll
        for (int j = 0; j < 4; j++) {
            const int n = n0 + tx * 4 + j;
            float v = vout[j] + (jb.bias ? jb.bias[n] : 0.f);
            if (jb.doRelu) v = fmaxf(v, 0.f);
            if (jb.doTrans) jb.C[n * MR + r] = v;
            else            jb.C[r * 256 + n] = v;
        }
    }
}

// ---------------- main pairwise-MLP kernel (fp16 mma, interleaved A-build) -----

// copy one full weight layer (128KB, 256 rows x 512B) into SM_W with swizzle
__device__ __forceinline__ void cp_layer(const char* __restrict__ src,
                                         uint32_t dstbase, int tid)
{
    #pragma unroll
    for (int i = 0; i < 16; i++) {
        int e = tid + i * 512;                 // 0..8191
        int k = e >> 5, u = e & 31;            // row (0..255), 16B unit
        uint32_t d = dstbase + (uint32_t)k * 512u + (uint32_t)((u ^ (k & 7)) << 4);
        asm volatile("cp.async.cg.shared.global [%0], [%1], 16;"
                     :: "r"(d), "l"(src + e * 16));
    }
    asm volatile("cp.async.commit_group;" ::: "memory");
}

// build 2 adjacent 16B units (g0, g0+1) of one A row: j0 = 8*g0 + quad*2
__device__ __forceinline__ void a_store_units(char* smp, int m, int quad, int g0,
                                              float v0, float v1, float v2, float v3)
{
    char* arow = smp + (uint32_t)m * 512u;
    uint32_t off0 = (uint32_t)(((g0 ^ (m & 7)) << 4) + quad * 4);
    *(uint32_t*)(arow + SM_A + off0) = f16x2bits(v0, v1);
    uint32_t off1 = (uint32_t)((((g0 + 1) ^ (m & 7)) << 4) + quad * 4);
    *(uint32_t*)(arow + SM_A + off1) = f16x2bits(v2, v3);
}

// Half of a 128x256x256 fp16 GEMM: 8 k16 steps starting at k16_0 (0 or 8).
// BUILD: builds A slice k16 = i+8 during iteration i (valid only for k16_0=0,
//        with a __syncthreads between the two halves).
// VAR:   accumulates 4 variance-dot terms per iteration, j = quad*64+vbase+i*4.
template<bool BUILD, bool VAR>
__device__ __forceinline__ void gemm_half(uint32_t abase, int k16_0,
                                          int warpM, int warpN, int lane,
                                          float (&acc)[2][8][4],
                                          char* smp, const float* __restrict__ qpb,
                                          const float* __restrict__ vqb,
                                          const float* __restrict__ wv2s,
                                          int rowb, float& vacc,
                                          int quad, int m, int vbase)
{
    const int rit  = (lane & 7) | (((lane >> 3) & 1) << 3); // row within 16-tile
    const int koff = lane >> 4;                              // 0/1: unit select
    uint32_t a_row[2]; uint32_t a_sw[2];
    #pragma unroll
    for (int mt = 0; mt < 2; mt++) {
        int rr = warpM * 32 + mt * 16 + rit;
        a_row[mt] = abase + (uint32_t)rr * 512u;
        a_sw[mt]  = (uint32_t)(rr & 7);
    }
    const uint32_t ksw = (uint32_t)(rit & 7);
    uint32_t boff[4];
    #pragma unroll
    for (int np = 0; np < 4; np++) {
        uint32_t nunit = (uint32_t)(warpN * 8 + np * 2 + koff);
        boff[np] = ((nunit ^ ksw) << 4);
    }
    const uint32_t browbase = abase + SM_W + (uint32_t)rit * 512u;

    // fragment double buffers: parity = i & 1 (k16_0 is even)
    uint32_t aF[2][2][4];
    uint32_t bF[2][2][4];
    #pragma unroll
    for (int mt = 0; mt < 2; mt++)
        ldsm_x4(aF[0][mt],
                a_row[mt] + (((uint32_t)(k16_0 * 2 + koff) ^ a_sw[mt]) << 4));
    {
        const uint32_t br0 = browbase + (uint32_t)k16_0 * 8192u;
        ldsm_x4_t(bF[0][0], br0 + boff[0]);
        ldsm_x4_t(bF[0][1], br0 + boff[1]);
    }

    #pragma unroll
    for (int i = 0; i < 8; i++) {
        const int k16 = k16_0 + i;
        const int s = i & 1;

        // ---- early global loads (latency hidden behind MMAs) ----
        float kp0, kp1, kp2, kp3;
        float vk0, vk1, vk2, vk3;
        int j0 = 0, jv = 0;
        if (BUILD) {
            int g0 = 2 * (i + 8);
            j0 = 8 * g0 + quad * 2;
            kp0 = g_kpT[j0 * MR + rowb];
            kp1 = g_kpT[(j0 + 1) * MR + rowb];
            kp2 = g_kpT[(j0 + 8) * MR + rowb];
            kp3 = g_kpT[(j0 + 9) * MR + rowb];
        }
        if (VAR) {
            jv = quad * 64 + vbase + i * 4;
            vk0 = g_vkT[jv * MR + rowb];
            vk1 = g_vkT[(jv + 1) * MR + rowb];
            vk2 = g_vkT[(jv + 2) * MR + rowb];
            vk3 = g_vkT[(jv + 3) * MR + rowb];
        }

        // ---- B np=2,3 for current k16 ----
        uint32_t bT[2][4];
        const uint32_t brow = browbase + (uint32_t)k16 * 8192u;
        ldsm_x4_t(bT[0], brow + boff[2]);
        ldsm_x4_t(bT[1], brow + boff[3]);

        // ---- MMA np=0,1 with pre-loaded fragments ----
        #pragma unroll
        for (int mt = 0; mt < 2; mt++) {
            mma_f16(acc[mt][0], aF[s][mt], bF[s][0][0], bF[s][0][1]);
            mma_f16(acc[mt][1], aF[s][mt], bF[s][0][2], bF[s][0][3]);
            mma_f16(acc[mt][2], aF[s][mt], bF[s][1][0], bF[s][1][1]);
            mma_f16(acc[mt][3], aF[s][mt], bF[s][1][2], bF[s][1][3]);
        }

        // ---- prefetch fragments for k16+1 (within this half only) ----
        if (i < 7) {
            #pragma unroll
            for (int mt = 0; mt < 2; mt++) {
                uint32_t unit = (uint32_t)((k16 + 1) * 2 + koff);
                ldsm_x4(aF[s ^ 1][mt], a_row[mt] + ((unit ^ a_sw[mt]) << 4));
            }
            const uint32_t brown = browbase + (uint32_t)(k16 + 1) * 8192u;
            ldsm_x4_t(bF[s ^ 1][0], brown + boff[0]);
            ldsm_x4_t(bF[s ^ 1][1], brown + boff[1]);
        }

        // ---- MMA np=2,3 ----
        #pragma unroll
        for (int mt = 0; mt < 2; mt++) {
            mma_f16(acc[mt][4], aF[s][mt], bT[0][0], bT[0][1]);
            mma_f16(acc[mt][5], aF[s][mt], bT[0][2], bT[0][3]);
            mma_f16(acc[mt][6], aF[s][mt], bT[1][0], bT[1][1]);
            mma_f16(acc[mt][7], aF[s][mt], bT[1][2], bT[1][3]);
        }

        // ---- late: A-build stores + variance FMAs ----
        if (BUILD) {
            int g0 = 2 * (i + 8);
            float v0 = fmaxf(qpb[j0]     + kp0, 0.f);
            float v1 = fmaxf(qpb[j0 + 1] + kp1, 0.f);
            float v2 = fmaxf(qpb[j0 + 8] + kp2, 0.f);
            float v3 = fmaxf(qpb[j0 + 9] + kp3, 0.f);
            a_store_units(smp, m, quad, g0, v0, v1, v2, v3);
        }
        if (VAR) {
            vacc = fmaf(fmaxf(vqb[jv]     + vk0, 0.f), wv2s[jv],     vacc);
            vacc = fmaf(fmaxf(vqb[jv + 1] + vk1, 0.f), wv2s[jv + 1], vacc);
            vacc = fmaf(fmaxf(vqb[jv + 2] + vk2, 0.f), wv2s[jv + 2], vacc);
            vacc = fmaf(fmaxf(vqb[jv + 3] + vk3, 0.f), wv2s[jv + 3], vacc);
        }
    }
}

__global__ __launch_bounds__(512, 1)
void pair_mma_kernel(const float* __restrict__ b1,  const float* __restrict__ b2,
                     const float* __restrict__ b3,  const float* __restrict__ Wf,
                     const float* __restrict__ bfp, const float* __restrict__ bv1,
                     const float* __restrict__ Wv2, const float* __restrict__ bv2,
                     float* __restrict__ out)
{
    extern __shared__ char smraw[];
    const uint32_t smbase = smem_u32(smraw);
    const uint32_t abase  = (smbase + 1023u) & ~1023u;
    char* smp = smraw + (abase - smbase);
    float* qpb  = (float*)(smp + SM_VEC);
    float* vqb  = qpb + 256;
    float* b2s  = vqb + 256;
    float* b3s  = b2s + 256;
    float* wfs  = b3s + 256;
    float* wv2s = wfs + 256;
    float* red  = wv2s + 256;   // 512 floats: [row][warpN]
    float* vred = red + 512;    // 512 floats: [key][p]

    const int tid   = threadIdx.x;
    const int lane  = tid & 31;
    const int w     = tid >> 5;
    const int warpM = w & 3, warpN = w >> 2;
    const int quad  = tid >> 7;
    const int m     = tid & 127;
    const int bid = blockIdx.x;
    const int kt  = bid & 3;
    const int q   = (bid >> 2) & 511;
    const int b   = bid >> 11;
    const int k0  = kt << 7;
    const int rowb  = b * SKK + k0 + m;
    const int lbase = (b * SQ + q) * SKK + k0;

    // start the full W2 copy immediately (128KB, async)
    cp_layer((const char*)g_Wh, abase + SM_W, tid);

    // vectors
    {
        const int r = (b * SQ + q) * HH;
        if (tid < 256) {
            qpb[tid] = g_qp[r + tid] + b1[tid];
            b2s[tid] = b2[tid];
            wfs[tid] = Wf[tid];
        } else {
            int u = tid & 255;
            vqb[u]  = g_vq[r + u] + bv1[u];
            b3s[u]  = b3[u];
            wv2s[u] = Wv2[u];
        }
    }
    __syncthreads();

    // ---- prebuild A slices k16 0..7 only (units 0..15), overlapping W2 copy ----
    {
        #pragma unroll 4
        for (int gg = 0; gg < 8; gg++) {
            int g0 = gg * 2;
            int j0 = 8 * g0 + quad * 2;
            float v0 = fmaxf(qpb[j0]     + g_kpT[j0 * MR + rowb],       0.f);
            float v1 = fmaxf(qpb[j0 + 1] + g_kpT[(j0 + 1) * MR + rowb], 0.f);
            float v2 = fmaxf(qpb[j0 + 8] + g_kpT[(j0 + 8) * MR + rowb], 0.f);
            float v3 = fmaxf(qpb[j0 + 9] + g_kpT[(j0 + 9) * MR + rowb], 0.f);
            a_store_units(smp, m, quad, g0, v0, v1, v2, v3);
        }
    }
    asm volatile("cp.async.wait_group 0;" ::: "memory");
    __syncthreads();

    // ---- GEMM 1: D = h0 @ W2 ----
    // first half (k16 0..7): builds A k16 8..15 + variance j 0..31 (per quad)
    float acc[2][8][4];
    #pragma unroll
    for (int i = 0; i < 2; i++)
        #pragma unroll
        for (int j = 0; j < 8; j++)
            #pragma unroll
            for (int e = 0; e < 4; e++) acc[i][j][e] = 0.f;
    float vacc = 0.f;
    gemm_half<true, true>(abase, 0, warpM, warpN, lane, acc,
                          smp, qpb, vqb, wv2s, rowb, vacc, quad, m, 0);
    __syncthreads();   // A k16 8..15 visible to all warps
    // second half (k16 8..15): variance j 32..63 (per quad)
    gemm_half<false, true>(abase, 8, warpM, warpN, lane, acc,
                           smp, qpb, vqb, wv2s, rowb, vacc, quad, m, 32);
    vred[m * 4 + quad] = vacc;
    __syncthreads();   // all W2 + h0 reads done; vred complete

    // start the full W3 copy (overlaps epilogue 1 + variance finalize)
    cp_layer((const char*)g_Wh + 131072, abase + SM_W, tid);

    // variance finalize
    if (tid < 128) {
        float s = vred[tid * 4] + vred[tid * 4 + 1] + vred[tid * 4 + 2] + vred[tid * 4 + 3]
                  + bv2[0];
        out[NTOT + lbase + tid] = softplusf(s);
    }

    // ---- epilogue 1: h1 = relu(D + b2) -> A buffer (fp16) ----
    {
        const int g  = lane >> 2;
        const int tg = lane & 3;
        #pragma unroll
        for (int mt = 0; mt < 2; mt++) {
            int r0 = warpM * 32 + mt * 16 + g;
            int r1 = r0 + 8;
            uint32_t row0 = (uint32_t)r0 * 512u;
            uint32_t row1 = (uint32_t)r1 * 512u;
            #pragma unroll
            for (int nt = 0; nt < 8; nt++) {
                int c0 = warpN * 64 + nt * 8 + tg * 2;
                float b20 = b2s[c0], b21 = b2s[c0 + 1];
                float v00 = fmaxf(acc[mt][nt][0] + b20, 0.f);
                float v01 = fmaxf(acc[mt][nt][1] + b21, 0.f);
                float v10 = fmaxf(acc[mt][nt][2] + b20, 0.f);
                float v11 = fmaxf(acc[mt][nt][3] + b21, 0.f);
                uint32_t unit = (uint32_t)(c0 >> 3);
                uint32_t o0 = row0 + ((unit ^ (uint32_t)(r0 & 7)) << 4) + (uint32_t)(tg * 4);
                uint32_t o1 = row1 + ((unit ^ (uint32_t)(r1 & 7)) << 4) + (uint32_t)(tg * 4);
                *(uint32_t*)(smp + SM_A + o0) = f16x2bits(v00, v01);
                *(uint32_t*)(smp + SM_A + o1) = f16x2bits(v10, v11);
            }
        }
    }
    asm volatile("cp.async.wait_group 0;" ::: "memory");
    __syncthreads();

    // ---- GEMM 2: D = h1 @ W3 (barrier-free, two plain halves) ----
    #pragma unroll
    for (int i = 0; i < 2; i++)
        #pragma unroll
        for (int j = 0; j < 8; j++)
            #pragma unroll
            for (int e = 0; e < 4; e++) acc[i][j][e] = 0.f;
    gemm_half<false, false>(abase, 0, warpM, warpN, lane, acc,
                            smp, qpb, vqb, wv2s, rowb, vacc, quad, m, 0);
    gemm_half<false, false>(abase, 8, warpM, warpN, lane, acc,
                            smp, qpb, vqb, wv2s, rowb, vacc, quad, m, 0);

    // ---- epilogue 2: logit = relu(D + b3) . Wf, cross-warp reduce ----
    {
        const int g  = lane >> 2;
        const int tg = lane & 3;
        #pragma unroll
        for (int mt = 0; mt < 2; mt++) {
            float lg0 = 0.f, lg1 = 0.f;
            #pragma unroll
            for (int nt = 0; nt < 8; nt++) {
                int c0 = warpN * 64 + nt * 8 + tg * 2;
                float b30 = b3s[c0], b31 = b3s[c0 + 1];
                float w0  = wfs[c0], w1  = wfs[c0 + 1];
                lg0 = fmaf(fmaxf(acc[mt][nt][0] + b30, 0.f), w0, lg0);
                lg0 = fmaf(fmaxf(acc[mt][nt][1] + b31, 0.f), w1, lg0);
                lg1 = fmaf(fmaxf(acc[mt][nt][2] + b30, 0.f), w0, lg1);
                lg1 = fmaf(fmaxf(acc[mt][nt][3] + b31, 0.f), w1, lg1);
            }
            lg0 += __shfl_xor_sync(0xffffffffu, lg0, 1);
            lg0 += __shfl_xor_sync(0xffffffffu, lg0, 2);
            lg1 += __shfl_xor_sync(0xffffffffu, lg1, 1);
            lg1 += __shfl_xor_sync(0xffffffffu, lg1, 2);
            if (tg == 0) {
                int r0 = warpM * 32 + mt * 16 + g;
                red[r0 * 4 + warpN]       = lg0;
                red[(r0 + 8) * 4 + warpN] = lg1;
            }
        }
    }
    __syncthreads();
    if (tid < 128) {
        float s = red[tid * 4] + red[tid * 4 + 1] + red[tid * 4 + 2] + red[tid * 4 + 3]
                  + bfp[0];
        out[lbase + tid] = s;
    }
}

// ---------------- launcher -----------------------------------------------------
extern "C" void kernel_launch(void* const* d_in, const int* in_sizes, int n_in,
                              void* d_out, int out_size)
{
    const float* query = (const float*)d_in[0];
    const float* key   = (const float*)d_in[1];
    const float* Wqe   = (const float*)d_in[2];
    const float* bqe   = (const float*)d_in[3];
    const float* Wke   = (const float*)d_in[4];
    const float* bke   = (const float*)d_in[5];
    const float* W1    = (const float*)d_in[6];
    const float* b1    = (const float*)d_in[7];
    const float* W2    = (const float*)d_in[8];
    const float* b2    = (const float*)d_in[9];
    const float* W3    = (const float*)d_in[10];
    const float* b3    = (const float*)d_in[11];
    const float* Wf    = (const float*)d_in[12];
    const float* bf    = (const float*)d_in[13];
    const float* Wv1   = (const float*)d_in[14];
    const float* bv1   = (const float*)d_in[15];
    const float* Wv2   = (const float*)d_in[16];
    const float* bv2   = (const float*)d_in[17];
    float* out = (float*)d_out;

    void *p_qf, *p_kf, *p_qp, *p_vq, *p_kpT, *p_vkT;
    cudaGetSymbolAddress(&p_qf,  g_qf);
    cudaGetSymbolAddress(&p_kf,  g_kf);
    cudaGetSymbolAddress(&p_qp,  g_qp);
    cudaGetSymbolAddress(&p_vq,  g_vq);
    cudaGetSymbolAddress(&p_kpT, g_kpT);
    cudaGetSymbolAddress(&p_vkT, g_vkT);

    // launch 1: encoders (z=0,1) + weight convert (z=2)
    ProjJob e0 { query, Wqe, bqe, (float*)p_qf, 0, 1, 0 };
    ProjJob e1 { key,   Wke, bke, (float*)p_kf, 0, 1, 0 };
    proj_batch_kernel<<<dim3(4, 16, 3), 256>>>(e0, e1, e0, e0, EE, W2, W3, 2);

    // launch 2: stage-2 projections
    ProjJob s0 { (const float*)p_qf, W1,  nullptr, (float*)p_qp,  0,   0, 0 };
    ProjJob s1 { (const float*)p_kf, W1,  nullptr, (float*)p_kpT, 256, 0, 1 };
    ProjJob s2 { (const float*)p_qf, Wv1, nullptr, (float*)p_vq,  0,   0, 0 };
    ProjJob s3 { (const float*)p_kf, Wv1, nullptr, (float*)p_vkT, 256, 0, 1 };
    proj_batch_kernel<<<dim3(4, 16, 4), 256>>>(s0, s1, s2, s3, HH, W2, W3, -1);

    // launch 3: main fused pairwise-MLP kernel
    cudaFuncSetAttribute(pair_mma_kernel,
                         cudaFuncAttributeMaxDynamicSharedMemorySize, SMEM_BYTES);
    pair_mma_kernel<<<BB * SQ * (SKK / 128), 512, SMEM_BYTES>>>(
        b1, b2, b3, Wf, bf, bv1, Wv2, bv2, out);
}

// round 15
// speedup vs baseline: 2.5550x; 1.0128x over previous
#include <cuda_runtime.h>
#include <cuda_bf16.h>
#include <cuda_fp16.h>
#include <math.h>
#include <stdint.h>

// Problem dims (fixed)
#define BB   2
#define SQ   512
#define SKK  512
#define EE   512
#define HH   256
#define MR   1024            // B*SQ = B*SK
#define NTOT (BB*SQ*SKK)     // 524288

// ---------------- scratch (device globals; no allocation allowed) -------------
__device__ float g_qf [MR*HH];
__device__ float g_kf [MR*HH];
__device__ float g_qp [MR*HH];
__device__ float g_vq [MR*HH];
__device__ float g_kpT[HH*MR];   // [H][B*SK]
__device__ float g_vkT[HH*MR];   // [H][B*SK]
// fp16 weight images: word layout [layer][k][nw] (nw = n/2, f16x2)
__device__ __align__(16) uint32_t g_Wh[2 * 256 * 128];

// SMEM map (byte offsets from 1024-aligned base)  -- main kernel
#define SM_A   0u        // 128 rows x 512B  (fp16 A) = 64KB
#define SM_W   65536u    // 256 rows x 512B  (full weight layer, fp16) = 128KB
#define SM_VEC 196608u
#define SMEM_BYTES (206848 + 1024)

// ---------------- PTX helpers --------------------------------------------------
__device__ __forceinline__ uint32_t smem_u32(const void* p) {
    return (uint32_t)__cvta_generic_to_shared(p);
}
__device__ __forceinline__ void ldsm_x4(uint32_t (&r)[4], uint32_t addr) {
    asm volatile("ldmatrix.sync.aligned.m8n8.x4.shared.b16 {%0,%1,%2,%3}, [%4];"
        : "=r"(r[0]), "=r"(r[1]), "=r"(r[2]), "=r"(r[3]) : "r"(addr));
}
__device__ __forceinline__ void ldsm_x4_t(uint32_t (&r)[4], uint32_t addr) {
    asm volatile("ldmatrix.sync.aligned.m8n8.x4.trans.shared.b16 {%0,%1,%2,%3}, [%4];"
        : "=r"(r[0]), "=r"(r[1]), "=r"(r[2]), "=r"(r[3]) : "r"(addr));
}
__device__ __forceinline__ void mma_f16(float (&d)[4], const uint32_t (&a)[4],
                                        uint32_t b0, uint32_t b1) {
    asm volatile("mma.sync.aligned.m16n8k16.row.col.f32.f16.f16.f32 "
        "{%0,%1,%2,%3}, {%4,%5,%6,%7}, {%8,%9}, {%0,%1,%2,%3};"
        : "+f"(d[0]), "+f"(d[1]), "+f"(d[2]), "+f"(d[3])
        : "r"(a[0]), "r"(a[1]), "r"(a[2]), "r"(a[3]), "r"(b0), "r"(b1));
}
__device__ __forceinline__ unsigned long long pack_dup(float a) {
    unsigned long long r;
    asm("mov.b64 %0, {%1, %1};" : "=l"(r) : "f"(a));
    return r;
}
__device__ __forceinline__ void unpack2(unsigned long long v, float& lo, float& hi) {
    asm("mov.b64 {%0, %1}, %2;" : "=f"(lo), "=f"(hi) : "l"(v));
}
__device__ __forceinline__ void ffma2(unsigned long long& acc, unsigned long long a,
                                      unsigned long long b) {
    asm("fma.rn.f32x2 %0, %1, %2, %0;" : "+l"(acc) : "l"(a), "l"(b));
}

// ---------------- small math helpers ------------------------------------------
__device__ __forceinline__ uint32_t f16x2bits(float v0, float v1) {
    __half2 h = __floats2half2_rn(v0, v1);
    return *reinterpret_cast<uint32_t*>(&h);
}
__device__ __forceinline__ float softplusf(float x) {
    if (x > 20.f) return x;
    return log1pf(expf(x));
}

// ---------------- prologue: batched 1024x256 projection GEMM (64x64 tiles) -----
// cp.async double-buffered A/W chunk staging; one barrier per K-chunk.
// blockIdx.z == wsplitZ runs the weight-convert instead (merged launch).
struct ProjJob {
    const float* A; const float* W; const float* bias; float* C;
    int wrow0; int doRelu; int doTrans;
};

#define PAS_LD 20   // As row stride (floats): 16 data + 4 pad

__device__ __forceinline__ void proj_stage_chunk(const float* __restrict__ A,
                                                 const float* __restrict__ W,
                                                 int K, int wrow0, int m0, int n0,
                                                 int kc, uint32_t asb, uint32_t wsb,
                                                 int tid)
{
    {
        int m = tid >> 2, seg = tid & 3;
        const float* src = A + (m0 + m) * K + kc + seg * 4;
        uint32_t dst = asb + (uint32_t)(m * PAS_LD + seg * 4) * 4u;
        asm volatile("cp.async.cg.shared.global [%0], [%1], 16;"
                     :: "r"(dst), "l"(src));
    }
    {
        int kk = tid >> 4, seg = tid & 15;
        const float* src = W + (wrow0 + kc + kk) * 256 + n0 + seg * 4;
        uint32_t dst = wsb + (uint32_t)(kk * 64 + seg * 4) * 4u;
        asm volatile("cp.async.cg.shared.global [%0], [%1], 16;"
                     :: "r"(dst), "l"(src));
    }
    asm volatile("cp.async.commit_group;" ::: "memory");
}

__global__ __launch_bounds__(256)
void proj_batch_kernel(ProjJob j0, ProjJob j1, ProjJob j2, ProjJob j3, int K,
                       const float* __restrict__ Wc2,
                       const float* __restrict__ Wc3, int wsplitZ)
{
    const int tid = threadIdx.x;
    if ((int)blockIdx.z == wsplitZ) {
        int base = (blockIdx.y * gridDim.x + blockIdx.x) * 256 + tid;
        #pragma unroll
        for (int i = 0; i < 4; i++) {
            int idx = base + i * 16384;
            int layer = idx >> 15;
            int rem   = idx & 32767;
            int k  = rem >> 7;
            int nw = rem & 127;
            const float* W = layer ? Wc3 : Wc2;
            g_Wh[idx] = f16x2bits(W[k * 256 + nw * 2], W[k * 256 + nw * 2 + 1]);
        }
        return;
    }
    ProjJob jb = (blockIdx.z == 0) ? j0 : (blockIdx.z == 1) ? j1 :
                 (blockIdx.z == 2) ? j2 : j3;
    __shared__ __align__(16) float As[2][64 * PAS_LD];
    __shared__ __align__(16) float Ws[2][16 * 64];
    const int m0  = blockIdx.y * 64;
    const int n0  = blockIdx.x * 64;
    const int ty  = tid >> 4, tx = tid & 15;

    const uint32_t asb0 = smem_u32(&As[0][0]), asb1 = smem_u32(&As[1][0]);
    const uint32_t wsb0 = smem_u32(&Ws[0][0]), wsb1 = smem_u32(&Ws[1][0]);

    unsigned long long acc2[4][2] = {};
    const int nch = K >> 4;

    proj_stage_chunk(jb.A, jb.W, K, jb.wrow0, m0, n0, 0, asb0, wsb0, tid);

    for (int ch = 0; ch < nch; ch++) {
        if (ch + 1 < nch)
            proj_stage_chunk(jb.A, jb.W, K, jb.wrow0, m0, n0, (ch + 1) << 4,
                             (ch & 1) ? asb0 : asb1, (ch & 1) ? wsb0 : wsb1, tid);
        if (ch + 1 < nch) { asm volatile("cp.async.wait_group 1;" ::: "memory"); }
        else              { asm volatile("cp.async.wait_group 0;" ::: "memory"); }
        __syncthreads();

        const float* Ab = As[ch & 1];
        const float* Wb = Ws[ch & 1];
        #pragma unroll
        for (int kk = 0; kk < 16; kk++) {
            unsigned long long w01 = *(const unsigned long long*)&Wb[kk * 64 + tx * 4];
            unsigned long long w23 = *(const unsigned long long*)&Wb[kk * 64 + tx * 4 + 2];
            #pragma unroll
            for (int i = 0; i < 4; i++) {
                unsigned long long ad = pack_dup(Ab[(ty * 4 + i) * PAS_LD + kk]);
                ffma2(acc2[i][0], ad, w01);
                ffma2(acc2[i][1], ad, w23);
            }
        }
        __syncthreads();
    }
    #pragma unroll
    for (int i = 0; i < 4; i++) {
        float vout[4];
        unpack2(acc2[i][0], vout[0], vout[1]);
        unpack2(acc2[i][1], vout[2], vout[3]);
        const int r = m0 + ty * 4 + i;
        #pragma unroll
        for (int j = 0; j < 4; j++) {
            const int n = n0 + tx * 4 + j;
            float v = vout[j] + (jb.bias ? jb.bias[n] : 0.f);
            if (jb.doRelu) v = fmaxf(v, 0.f);
            if (jb.doTrans) jb.C[n * MR + r] = v;
            else            jb.C[r * 256 + n] = v;
        }
    }
}

// ---------------- main pairwise-MLP kernel (fp16 mma, split-layer W copies) ----

// copy HALF of a weight layer (64KB, rows half*128..half*128+127) into SM_W
__device__ __forceinline__ void cp_half(const char* __restrict__ src,
                                        uint32_t dstbase, int half, int tid)
{
    const char* s = src + half * 65536;
    #pragma unroll
    for (int i = 0; i < 8; i++) {
        int e = tid + i * 512;                 // 0..4095
        int kl = e >> 5, u = e & 31;           // local row (0..127), 16B unit
        int k = kl + half * 128;               // global row
        uint32_t d = dstbase + (uint32_t)k * 512u + (uint32_t)((u ^ (k & 7)) << 4);
        asm volatile("cp.async.cg.shared.global [%0], [%1], 16;"
                     :: "r"(d), "l"(s + e * 16));
    }
    asm volatile("cp.async.commit_group;" ::: "memory");
}

// build 2 adjacent 16B units (g0, g0+1) of one A row: j0 = 8*g0 + quad*2
__device__ __forceinline__ void a_store_units(char* smp, int m, int quad, int g0,
                                              float v0, float v1, float v2, float v3)
{
    char* arow = smp + (uint32_t)m * 512u;
    uint32_t off0 = (uint32_t)(((g0 ^ (m & 7)) << 4) + quad * 4);
    *(uint32_t*)(arow + SM_A + off0) = f16x2bits(v0, v1);
    uint32_t off1 = (uint32_t)((((g0 + 1) ^ (m & 7)) << 4) + quad * 4);
    *(uint32_t*)(arow + SM_A + off1) = f16x2bits(v2, v3);
}

// Half of a 128x256x256 fp16 GEMM: 8 k16 steps starting at k16_0 (0 or 8).
// BUILD: builds A slice k16 = i+8 during iteration i (valid only for k16_0=0,
//        with a __syncthreads between the two halves).
// VAR:   accumulates 4 variance-dot terms per iteration, j = quad*64+vbase+i*4.
template<bool BUILD, bool VAR>
__device__ __forceinline__ void gemm_half(uint32_t abase, int k16_0,
                                          int warpM, int warpN, int lane,
                                          float (&acc)[2][8][4],
                                          char* smp, const float* __restrict__ qpb,
                                          const float* __restrict__ vqb,
                                          const float* __restrict__ wv2s,
                                          int rowb, float& vacc,
                                          int quad, int m, int vbase)
{
    const int rit  = (lane & 7) | (((lane >> 3) & 1) << 3); // row within 16-tile
    const int koff = lane >> 4;                              // 0/1: unit select
    uint32_t a_row[2]; uint32_t a_sw[2];
    #pragma unroll
    for (int mt = 0; mt < 2; mt++) {
        int rr = warpM * 32 + mt * 16 + rit;
        a_row[mt] = abase + (uint32_t)rr * 512u;
        a_sw[mt]  = (uint32_t)(rr & 7);
    }
    const uint32_t ksw = (uint32_t)(rit & 7);
    uint32_t boff[4];
    #pragma unroll
    for (int np = 0; np < 4; np++) {
        uint32_t nunit = (uint32_t)(warpN * 8 + np * 2 + koff);
        boff[np] = ((nunit ^ ksw) << 4);
    }
    const uint32_t browbase = abase + SM_W + (uint32_t)rit * 512u;

    // fragment double buffers: parity = i & 1 (k16_0 is even)
    uint32_t aF[2][2][4];
    uint32_t bF[2][2][4];
    #pragma unroll
    for (int mt = 0; mt < 2; mt++)
        ldsm_x4(aF[0][mt],
                a_row[mt] + (((uint32_t)(k16_0 * 2 + koff) ^ a_sw[mt]) << 4));
    {
        const uint32_t br0 = browbase + (uint32_t)k16_0 * 8192u;
        ldsm_x4_t(bF[0][0], br0 + boff[0]);
        ldsm_x4_t(bF[0][1], br0 + boff[1]);
    }

    #pragma unroll
    for (int i = 0; i < 8; i++) {
        const int k16 = k16_0 + i;
        const int s = i & 1;

        // ---- early global loads (latency hidden behind MMAs) ----
        float kp0, kp1, kp2, kp3;
        float vk0, vk1, vk2, vk3;
        int j0 = 0, jv = 0;
        if (BUILD) {
            int g0 = 2 * (i + 8);
            j0 = 8 * g0 + quad * 2;
            kp0 = g_kpT[j0 * MR + rowb];
            kp1 = g_kpT[(j0 + 1) * MR + rowb];
            kp2 = g_kpT[(j0 + 8) * MR + rowb];
            kp3 = g_kpT[(j0 + 9) * MR + rowb];
        }
        if (VAR) {
            jv = quad * 64 + vbase + i * 4;
            vk0 = g_vkT[jv * MR + rowb];
            vk1 = g_vkT[(jv + 1) * MR + rowb];
            vk2 = g_vkT[(jv + 2) * MR + rowb];
            vk3 = g_vkT[(jv + 3) * MR + rowb];
        }

        // ---- B np=2,3 for current k16 ----
        uint32_t bT[2][4];
        const uint32_t brow = browbase + (uint32_t)k16 * 8192u;
        ldsm_x4_t(bT[0], brow + boff[2]);
        ldsm_x4_t(bT[1], brow + boff[3]);

        // ---- MMA np=0,1 with pre-loaded fragments ----
        #pragma unroll
        for (int mt = 0; mt < 2; mt++) {
            mma_f16(acc[mt][0], aF[s][mt], bF[s][0][0], bF[s][0][1]);
            mma_f16(acc[mt][1], aF[s][mt], bF[s][0][2], bF[s][0][3]);
            mma_f16(acc[mt][2], aF[s][mt], bF[s][1][0], bF[s][1][1]);
            mma_f16(acc[mt][3], aF[s][mt], bF[s][1][2], bF[s][1][3]);
        }

        // ---- prefetch fragments for k16+1 (within this half only) ----
        if (i < 7) {
            #pragma unroll
            for (int mt = 0; mt < 2; mt++) {
                uint32_t unit = (uint32_t)((k16 + 1) * 2 + koff);
                ldsm_x4(aF[s ^ 1][mt], a_row[mt] + ((unit ^ a_sw[mt]) << 4));
            }
            const uint32_t brown = browbase + (uint32_t)(k16 + 1) * 8192u;
            ldsm_x4_t(bF[s ^ 1][0], brown + boff[0]);
            ldsm_x4_t(bF[s ^ 1][1], brown + boff[1]);
        }

        // ---- MMA np=2,3 ----
        #pragma unroll
        for (int mt = 0; mt < 2; mt++) {
            mma_f16(acc[mt][4], aF[s][mt], bT[0][0], bT[0][1]);
            mma_f16(acc[mt][5], aF[s][mt], bT[0][2], bT[0][3]);
            mma_f16(acc[mt][6], aF[s][mt], bT[1][0], bT[1][1]);
            mma_f16(acc[mt][7], aF[s][mt], bT[1][2], bT[1][3]);
        }

        // ---- late: A-build stores + variance FMAs ----
        if (BUILD) {
            int g0 = 2 * (i + 8);
            float v0 = fmaxf(qpb[j0]     + kp0, 0.f);
            float v1 = fmaxf(qpb[j0 + 1] + kp1, 0.f);
            float v2 = fmaxf(qpb[j0 + 8] + kp2, 0.f);
            float v3 = fmaxf(qpb[j0 + 9] + kp3, 0.f);
            a_store_units(smp, m, quad, g0, v0, v1, v2, v3);
        }
        if (VAR) {
            vacc = fmaf(fmaxf(vqb[jv]     + vk0, 0.f), wv2s[jv],     vacc);
            vacc = fmaf(fmaxf(vqb[jv + 1] + vk1, 0.f), wv2s[jv + 1], vacc);
            vacc = fmaf(fmaxf(vqb[jv + 2] + vk2, 0.f), wv2s[jv + 2], vacc);
            vacc = fmaf(fmaxf(vqb[jv + 3] + vk3, 0.f), wv2s[jv + 3], vacc);
        }
    }
}

__global__ __launch_bounds__(512, 1)
void pair_mma_kernel(const float* __restrict__ b1,  const float* __restrict__ b2,
                     const float* __restrict__ b3,  const float* __restrict__ Wf,
                     const float* __restrict__ bfp, const float* __restrict__ bv1,
                     const float* __restrict__ Wv2, const float* __restrict__ bv2,
                     float* __restrict__ out)
{
    extern __shared__ char smraw[];
    const uint32_t smbase = smem_u32(smraw);
    const uint32_t abase  = (smbase + 1023u) & ~1023u;
    char* smp = smraw + (abase - smbase);
    float* qpb  = (float*)(smp + SM_VEC);
    float* vqb  = qpb + 256;
    float* b2s  = vqb + 256;
    float* b3s  = b2s + 256;
    float* wfs  = b3s + 256;
    float* wv2s = wfs + 256;
    float* red  = wv2s + 256;   // 512 floats: [row][warpN]
    float* vred = red + 512;    // 512 floats: [key][p]

    const int tid   = threadIdx.x;
    const int lane  = tid & 31;
    const int w     = tid >> 5;
    const int warpM = w & 3, warpN = w >> 2;
    const int quad  = tid >> 7;
    const int m     = tid & 127;
    const int bid = blockIdx.x;
    const int kt  = bid & 3;
    const int q   = (bid >> 2) & 511;
    const int b   = bid >> 11;
    const int k0  = kt << 7;
    const int rowb  = b * SKK + k0 + m;
    const int lbase = (b * SQ + q) * SKK + k0;

    const char* W2src = (const char*)g_Wh;
    const char* W3src = (const char*)g_Wh + 131072;

    // start W2 copy immediately as two 64KB halves (groups 0,1)
    cp_half(W2src, abase + SM_W, 0, tid);
    cp_half(W2src, abase + SM_W, 1, tid);

    // vectors
    {
        const int r = (b * SQ + q) * HH;
        if (tid < 256) {
            qpb[tid] = g_qp[r + tid] + b1[tid];
            b2s[tid] = b2[tid];
            wfs[tid] = Wf[tid];
        } else {
            int u = tid & 255;
            vqb[u]  = g_vq[r + u] + bv1[u];
            b3s[u]  = b3[u];
            wv2s[u] = Wv2[u];
        }
    }
    __syncthreads();

    // ---- prebuild A slices k16 0..7 only, overlapping the W2 copy ----
    {
        #pragma unroll 4
        for (int gg = 0; gg < 8; gg++) {
            int g0 = gg * 2;
            int j0 = 8 * g0 + quad * 2;
            float v0 = fmaxf(qpb[j0]     + g_kpT[j0 * MR + rowb],       0.f);
            float v1 = fmaxf(qpb[j0 + 1] + g_kpT[(j0 + 1) * MR + rowb], 0.f);
            float v2 = fmaxf(qpb[j0 + 8] + g_kpT[(j0 + 8) * MR + rowb], 0.f);
            float v3 = fmaxf(qpb[j0 + 9] + g_kpT[(j0 + 9) * MR + rowb], 0.f);
            a_store_units(smp, m, quad, g0, v0, v1, v2, v3);
        }
    }
    asm volatile("cp.async.wait_group 1;" ::: "memory");   // W2-lo ready
    __syncthreads();

    // ---- GEMM 1: D = h0 @ W2 ----
    float acc[2][8][4];
    #pragma unroll
    for (int i = 0; i < 2; i++)
        #pragma unroll
        for (int j = 0; j < 8; j++)
            #pragma unroll
            for (int e = 0; e < 4; e++) acc[i][j][e] = 0.f;
    float vacc = 0.f;
    // half1 (k16 0..7, W2 rows 0..127): builds A k16 8..15 + variance j 0..31
    gemm_half<true, true>(abase, 0, warpM, warpN, lane, acc,
                          smp, qpb, vqb, wv2s, rowb, vacc, quad, m, 0);
    asm volatile("cp.async.wait_group 0;" ::: "memory");   // W2-hi ready
    __syncthreads();   // A k16 8..15 visible; W2-lo reads all done
    // W2-lo dead -> stream W3-lo in during half2 (group 2)
    cp_half(W3src, abase + SM_W, 0, tid);
    // half2 (k16 8..15, W2 rows 128..255): variance j 32..63
    gemm_half<false, true>(abase, 8, warpM, warpN, lane, acc,
                           smp, qpb, vqb, wv2s, rowb, vacc, quad, m, 32);
    vred[m * 4 + quad] = vacc;
    __syncthreads();   // all W2 + h0 reads done; vred complete

    // W2-hi dead -> stream W3-hi in during epilogue (group 3)
    cp_half(W3src, abase + SM_W, 1, tid);

    // variance finalize
    if (tid < 128) {
        float s = vred[tid * 4] + vred[tid * 4 + 1] + vred[tid * 4 + 2] + vred[tid * 4 + 3]
                  + bv2[0];
        out[NTOT + lbase + tid] = softplusf(s);
    }

    // ---- epilogue 1: h1 = relu(D + b2) -> A buffer (fp16) ----
    {
        const int g  = lane >> 2;
        const int tg = lane & 3;
        #pragma unroll
        for (int mt = 0; mt < 2; mt++) {
            int r0 = warpM * 32 + mt * 16 + g;
            int r1 = r0 + 8;
            uint32_t row0 = (uint32_t)r0 * 512u;
            uint32_t row1 = (uint32_t)r1 * 512u;
            #pragma unroll
            for (int nt = 0; nt < 8; nt++) {
                int c0 = warpN * 64 + nt * 8 + tg * 2;
                float b20 = b2s[c0], b21 = b2s[c0 + 1];
                float v00 = fmaxf(acc[mt][nt][0] + b20, 0.f);
                float v01 = fmaxf(acc[mt][nt][1] + b21, 0.f);
                float v10 = fmaxf(acc[mt][nt][2] + b20, 0.f);
                float v11 = fmaxf(acc[mt][nt][3] + b21, 0.f);
                uint32_t unit = (uint32_t)(c0 >> 3);
                uint32_t o0 = row0 + ((unit ^ (uint32_t)(r0 & 7)) << 4) + (uint32_t)(tg * 4);
                uint32_t o1 = row1 + ((unit ^ (uint32_t)(r1 & 7)) << 4) + (uint32_t)(tg * 4);
                *(uint32_t*)(smp + SM_A + o0) = f16x2bits(v00, v01);
                *(uint32_t*)(smp + SM_A + o1) = f16x2bits(v10, v11);
            }
        }
    }
    asm volatile("cp.async.wait_group 1;" ::: "memory");   // W3-lo ready
    __syncthreads();

    // ---- GEMM 2: D = h1 @ W3 ----
    #pragma unroll
    for (int i = 0; i < 2; i++)
        #pragma unroll
        for (int j = 0; j < 8; j++)
            #pragma unroll
            for (int e = 0; e < 4; e++) acc[i][j][e] = 0.f;
    gemm_half<false, false>(abase, 0, warpM, warpN, lane, acc,
                            smp, qpb, vqb, wv2s, rowb, vacc, quad, m, 0);
    asm volatile("cp.async.wait_group 0;" ::: "memory");   // W3-hi ready
    __syncthreads();
    gemm_half<false, false>(abase, 8, warpM, warpN, lane, acc,
                            smp, qpb, vqb, wv2s, rowb, vacc, quad, m, 0);

    // ---- epilogue 2: logit = relu(D + b3) . Wf, cross-warp reduce ----
    {
        const int g  = lane >> 2;
        const int tg = lane & 3;
        #pragma unroll
        for (int mt = 0; mt < 2; mt++) {
            float lg0 = 0.f, lg1 = 0.f;
            #pragma unroll
            for (int nt = 0; nt < 8; nt++) {
                int c0 = warpN * 64 + nt * 8 + tg * 2;
                float b30 = b3s[c0], b31 = b3s[c0 + 1];
                float w0  = wfs[c0], w1  = wfs[c0 + 1];
                lg0 = fmaf(fmaxf(acc[mt][nt][0] + b30, 0.f), w0, lg0);
                lg0 = fmaf(fmaxf(acc[mt][nt][1] + b31, 0.f), w1, lg0);
                lg1 = fmaf(fmaxf(acc[mt][nt][2] + b30, 0.f), w0, lg1);
                lg1 = fmaf(fmaxf(acc[mt][nt][3] + b31, 0.f), w1, lg1);
            }
            lg0 += __shfl_xor_sync(0xffffffffu, lg0, 1);
            lg0 += __shfl_xor_sync(0xffffffffu, lg0, 2);
            lg1 += __shfl_xor_sync(0xffffffffu, lg1, 1);
            lg1 += __shfl_xor_sync(0xffffffffu, lg1, 2);
            if (tg == 0) {
                int r0 = warpM * 32 + mt * 16 + g;
                red[r0 * 4 + warpN]       = lg0;
                red[(r0 + 8) * 4 + warpN] = lg1;
            }
        }
    }
    __syncthreads();
    if (tid < 128) {
        float s = red[tid * 4] + red[tid * 4 + 1] + red[tid * 4 + 2] + red[tid * 4 + 3]
                  + bfp[0];
        out[lbase + tid] = s;
    }
}

// ---------------- launcher -----------------------------------------------------
extern "C" void kernel_launch(void* const* d_in, const int* in_sizes, int n_in,
                              void* d_out, int out_size)
{
    const float* query = (const float*)d_in[0];
    const float* key   = (const float*)d_in[1];
    const float* Wqe   = (const float*)d_in[2];
    const float* bqe   = (const float*)d_in[3];
    const float* Wke   = (const float*)d_in[4];
    const float* bke   = (const float*)d_in[5];
    const float* W1    = (const float*)d_in[6];
    const float* b1    = (const float*)d_in[7];
    const float* W2    = (const float*)d_in[8];
    const float* b2    = (const float*)d_in[9];
    const float* W3    = (const float*)d_in[10];
    const float* b3    = (const float*)d_in[11];
    const float* Wf    = (const float*)d_in[12];
    const float* bf    = (const float*)d_in[13];
    const float* Wv1   = (const float*)d_in[14];
    const float* bv1   = (const float*)d_in[15];
    const float* Wv2   = (const float*)d_in[16];
    const float* bv2   = (const float*)d_in[17];
    float* out = (float*)d_out;

    void *p_qf, *p_kf, *p_qp, *p_vq, *p_kpT, *p_vkT;
    cudaGetSymbolAddress(&p_qf,  g_qf);
    cudaGetSymbolAddress(&p_kf,  g_kf);
    cudaGetSymbolAddress(&p_qp,  g_qp);
    cudaGetSymbolAddress(&p_vq,  g_vq);
    cudaGetSymbolAddress(&p_kpT, g_kpT);
    cudaGetSymbolAddress(&p_vkT, g_vkT);

    // launch 1: encoders (z=0,1) + weight convert (z=2)
    ProjJob e0 { query, Wqe, bqe, (float*)p_qf, 0, 1, 0 };
    ProjJob e1 { key,   Wke, bke, (float*)p_kf, 0, 1, 0 };
    proj_batch_kernel<<<dim3(4, 16, 3), 256>>>(e0, e1, e0, e0, EE, W2, W3, 2);

    // launch 2: stage-2 projections
    ProjJob s0 { (const float*)p_qf, W1,  nullptr, (float*)p_qp,  0,   0, 0 };
    ProjJob s1 { (const float*)p_kf, W1,  nullptr, (float*)p_kpT, 256, 0, 1 };
    ProjJob s2 { (const float*)p_qf, Wv1, nullptr, (float*)p_vq,  0,   0, 0 };
    ProjJob s3 { (const float*)p_kf, Wv1, nullptr, (float*)p_vkT, 256, 0, 1 };
    proj_batch_kernel<<<dim3(4, 16, 4), 256>>>(s0, s1, s2, s3, HH, W2, W3, -1);

    // launch 3: main fused pairwise-MLP kernel (split-layer W streaming)
    cudaFuncSetAttribute(pair_mma_kernel,
                         cudaFuncAttributeMaxDynamicSharedMemorySize, SMEM_BYTES);
    pair_mma_kernel<<<BB * SQ * (SKK / 128), 512, SMEM_BYTES>>>(
        b1, b2, b3, Wf, bf, bv1, Wv2, bv2, out);
}

// round 16
// speedup vs baseline: 2.5783x; 1.0091x over previous
#include <cuda_runtime.h>
#include <cuda_bf16.h>
#include <cuda_fp16.h>
#include <math.h>
#include <stdint.h>

// Problem dims (fixed)
#define BB   2
#define SQ   512
#define SKK  512
#define EE   512
#define HH   256
#define MR   1024            // B*SQ = B*SK
#define NTOT (BB*SQ*SKK)     // 524288

// ---------------- scratch (device globals; no allocation allowed) -------------
__device__ float g_qf [MR*HH];
__device__ float g_kf [MR*HH];
__device__ float g_qp [MR*HH];
__device__ float g_vq [MR*HH];
__device__ float g_kpT[HH*MR];   // [H][B*SK]
__device__ float g_vkT[HH*MR];   // [H][B*SK]
// fp16 weight images: word layout [layer][k][nw] (nw = n/2, f16x2)
__device__ __align__(16) uint32_t g_Wh[2 * 256 * 128];

// SMEM map (byte offsets from 1024-aligned base)  -- main kernel
#define SM_A   0u        // 128 rows x 512B  (fp16 A) = 64KB
#define SM_W   65536u    // 256 rows x 512B  (full weight layer, fp16) = 128KB
#define SM_VEC 196608u
#define SMEM_BYTES (206848 + 1024)

// proj kernel dynamic smem: As 3 x (64*36) + Ws 3 x (32*64) floats
#define PROJ_AS_STRIDE 2304
#define PROJ_WS_STRIDE 2048
#define PROJ_WS_OFF    (3 * PROJ_AS_STRIDE)
#define PROJ_SMEM_BYTES ((3 * PROJ_AS_STRIDE + 3 * PROJ_WS_STRIDE) * 4)

// ---------------- PTX helpers --------------------------------------------------
__device__ __forceinline__ uint32_t smem_u32(const void* p) {
    return (uint32_t)__cvta_generic_to_shared(p);
}
__device__ __forceinline__ void ldsm_x4(uint32_t (&r)[4], uint32_t addr) {
    asm volatile("ldmatrix.sync.aligned.m8n8.x4.shared.b16 {%0,%1,%2,%3}, [%4];"
        : "=r"(r[0]), "=r"(r[1]), "=r"(r[2]), "=r"(r[3]) : "r"(addr));
}
__device__ __forceinline__ void ldsm_x4_t(uint32_t (&r)[4], uint32_t addr) {
    asm volatile("ldmatrix.sync.aligned.m8n8.x4.trans.shared.b16 {%0,%1,%2,%3}, [%4];"
        : "=r"(r[0]), "=r"(r[1]), "=r"(r[2]), "=r"(r[3]) : "r"(addr));
}
__device__ __forceinline__ void mma_f16(float (&d)[4], const uint32_t (&a)[4],
                                        uint32_t b0, uint32_t b1) {
    asm volatile("mma.sync.aligned.m16n8k16.row.col.f32.f16.f16.f32 "
        "{%0,%1,%2,%3}, {%4,%5,%6,%7}, {%8,%9}, {%0,%1,%2,%3};"
        : "+f"(d[0]), "+f"(d[1]), "+f"(d[2]), "+f"(d[3])
        : "r"(a[0]), "r"(a[1]), "r"(a[2]), "r"(a[3]), "r"(b0), "r"(b1));
}
__device__ __forceinline__ unsigned long long pack_dup(float a) {
    unsigned long long r;
    asm("mov.b64 %0, {%1, %1};" : "=l"(r) : "f"(a));
    return r;
}
__device__ __forceinline__ void unpack2(unsigned long long v, float& lo, float& hi) {
    asm("mov.b64 {%0, %1}, %2;" : "=f"(lo), "=f"(hi) : "l"(v));
}
__device__ __forceinline__ void ffma2(unsigned long long& acc, unsigned long long a,
                                      unsigned long long b) {
    asm("fma.rn.f32x2 %0, %1, %2, %0;" : "+l"(acc) : "l"(a), "l"(b));
}

// ---------------- small math helpers ------------------------------------------
__device__ __forceinline__ uint32_t f16x2bits(float v0, float v1) {
    __half2 h = __floats2half2_rn(v0, v1);
    return *reinterpret_cast<uint32_t*>(&h);
}
__device__ __forceinline__ float softplusf(float x) {
    if (x > 20.f) return x;
    return log1pf(expf(x));
}

// ---------------- prologue: batched 1024x256 projection GEMM -------------------
// 64x64 tiles, K-chunk 32, 3-stage cp.async pipeline, ONE barrier per chunk.
// blockIdx.z == wsplitZ runs the weight-convert instead (merged launch).
struct ProjJob {
    const float* A; const float* W; const float* bias; float* C;
    int wrow0; int doRelu; int doTrans;
};

__device__ __forceinline__ void proj_stage_chunk(const float* __restrict__ A,
                                                 const float* __restrict__ W,
                                                 int K, int wrow0, int m0, int n0,
                                                 int c, float* As, float* Ws,
                                                 int tid)
{
    const int kc = c << 5;
    const int buf = c % 3;
    const uint32_t asb = smem_u32(As + buf * PROJ_AS_STRIDE);
    const uint32_t wsb = smem_u32(Ws + buf * PROJ_WS_STRIDE);
    // A chunk: 64 rows x 32 floats (8 x 16B per row); 2 units/thread
    #pragma unroll
    for (int i = 0; i < 2; i++) {
        int e = tid + i * 256;              // 0..511
        int m = e >> 3, seg = e & 7;
        const float* src = A + (m0 + m) * K + kc + seg * 4;
        uint32_t dst = asb + (uint32_t)(m * 36 + seg * 4) * 4u;
        asm volatile("cp.async.cg.shared.global [%0], [%1], 16;"
                     :: "r"(dst), "l"(src));
    }
    // W chunk: 32 k-rows x 64 floats (16 x 16B per row); 2 units/thread
    #pragma unroll
    for (int i = 0; i < 2; i++) {
        int e = tid + i * 256;              // 0..511
        int kk = e >> 4, seg = e & 15;
        const float* src = W + (wrow0 + kc + kk) * 256 + n0 + seg * 4;
        uint32_t dst = wsb + (uint32_t)(kk * 64 + seg * 4) * 4u;
        asm volatile("cp.async.cg.shared.global [%0], [%1], 16;"
                     :: "r"(dst), "l"(src));
    }
    asm volatile("cp.async.commit_group;" ::: "memory");
}

__global__ __launch_bounds__(256)
void proj_batch_kernel(ProjJob j0, ProjJob j1, ProjJob j2, ProjJob j3, int K,
                       const float* __restrict__ Wc2,
                       const float* __restrict__ Wc3, int wsplitZ)
{
    const int tid = threadIdx.x;
    if ((int)blockIdx.z == wsplitZ) {
        int base = (blockIdx.y * gridDim.x + blockIdx.x) * 256 + tid;
        #pragma unroll
        for (int i = 0; i < 4; i++) {
            int idx = base + i * 16384;
            int layer = idx >> 15;
            int rem   = idx & 32767;
            int k  = rem >> 7;
            int nw = rem & 127;
            const float* W = layer ? Wc3 : Wc2;
            g_Wh[idx] = f16x2bits(W[k * 256 + nw * 2], W[k * 256 + nw * 2 + 1]);
        }
        return;
    }
    ProjJob jb = (blockIdx.z == 0) ? j0 : (blockIdx.z == 1) ? j1 :
                 (blockIdx.z == 2) ? j2 : j3;
    extern __shared__ float psm[];
    float* As = psm;                    // 3 bufs x 64x36
    float* Ws = psm + PROJ_WS_OFF;      // 3 bufs x 32x64
    const int m0  = blockIdx.y * 64;
    const int n0  = blockIdx.x * 64;
    const int ty  = tid >> 4, tx = tid & 15;

    unsigned long long acc2[4][2] = {};
    const int nch = K >> 5;

    proj_stage_chunk(jb.A, jb.W, K, jb.wrow0, m0, n0, 0, As, Ws, tid);
    proj_stage_chunk(jb.A, jb.W, K, jb.wrow0, m0, n0, 1, As, Ws, tid);

    for (int ch = 0; ch < nch; ch++) {
        if (ch + 1 < nch) { asm volatile("cp.async.wait_group 1;" ::: "memory"); }
        else              { asm volatile("cp.async.wait_group 0;" ::: "memory"); }
        __syncthreads();
        if (ch + 2 < nch)
            proj_stage_chunk(jb.A, jb.W, K, jb.wrow0, m0, n0, ch + 2, As, Ws, tid);

        const float* Ab = As + (ch % 3) * PROJ_AS_STRIDE;
        const float* Wb = Ws + (ch % 3) * PROJ_WS_STRIDE;
        #pragma unroll
        for (int kk = 0; kk < 32; kk++) {
            unsigned long long w01 = *(const unsigned long long*)&Wb[kk * 64 + tx * 4];
            unsigned long long w23 = *(const unsigned long long*)&Wb[kk * 64 + tx * 4 + 2];
            #pragma unroll
            for (int i = 0; i < 4; i++) {
                unsigned long long ad = pack_dup(Ab[(ty * 4 + i) * 36 + kk]);
                ffma2(acc2[i][0], ad, w01);
                ffma2(acc2[i][1], ad, w23);
            }
        }
    }
    #pragma unroll
    for (int i = 0; i < 4; i++) {
        float vout[4];
        unpack2(acc2[i][0], vout[0], vout[1]);
        unpack2(acc2[i][1], vout[2], vout[3]);
        const int r = m0 + ty * 4 + i;
        #pragma unroll
        for (int j = 0; j < 4; j++) {
            const int n = n0 + tx * 4 + j;
            float v = vout[j] + (jb.bias ? jb.bias[n] : 0.f);
            if (jb.doRelu) v = fmaxf(v, 0.f);
            if (jb.doTrans) jb.C[n * MR + r] = v;
            else            jb.C[r * 256 + n] = v;
        }
    }
}

// ---------------- main pairwise-MLP kernel (fp16 mma, split-layer W copies) ----

// copy HALF of a weight layer (64KB, rows half*128..half*128+127) into SM_W
__device__ __forceinline__ void cp_half(const char* __restrict__ src,
                                        uint32_t dstbase, int half, int tid)
{
    const char* s = src + half * 65536;
    #pragma unroll
    for (int i = 0; i < 8; i++) {
        int e = tid + i * 512;                 // 0..4095
        int kl = e >> 5, u = e & 31;           // local row (0..127), 16B unit
        int k = kl + half * 128;               // global row
        uint32_t d = dstbase + (uint32_t)k * 512u + (uint32_t)((u ^ (k & 7)) << 4);
        asm volatile("cp.async.cg.shared.global [%0], [%1], 16;"
                     :: "r"(d), "l"(s + e * 16));
    }
    asm volatile("cp.async.commit_group;" ::: "memory");
}

// build 2 adjacent 16B units (g0, g0+1) of one A row: j0 = 8*g0 + quad*2
__device__ __forceinline__ void a_store_units(char* smp, int m, int quad, int g0,
                                              float v0, float v1, float v2, float v3)
{
    char* arow = smp + (uint32_t)m * 512u;
    uint32_t off0 = (uint32_t)(((g0 ^ (m & 7)) << 4) + quad * 4);
    *(uint32_t*)(arow + SM_A + off0) = f16x2bits(v0, v1);
    uint32_t off1 = (uint32_t)((((g0 + 1) ^ (m & 7)) << 4) + quad * 4);
    *(uint32_t*)(arow + SM_A + off1) = f16x2bits(v2, v3);
}

// Half of a 128x256x256 fp16 GEMM: 8 k16 steps starting at k16_0 (0 or 8).
// BUILD: builds A slice k16 = i+8 during iteration i (valid only for k16_0=0,
//        with a __syncthreads between the two halves).
// VAR:   accumulates 4 variance-dot terms per iteration, j = quad*64+vbase+i*4.
template<bool BUILD, bool VAR>
__device__ __forceinline__ void gemm_half(uint32_t abase, int k16_0,
                                          int warpM, int warpN, int lane,
                                          float (&acc)[2][8][4],
                                          char* smp, const float* __restrict__ qpb,
                                          const float* __restrict__ vqb,
                                          const float* __restrict__ wv2s,
                                          int rowb, float& vacc,
                                          int quad, int m, int vbase)
{
    const int rit  = (lane & 7) | (((lane >> 3) & 1) << 3); // row within 16-tile
    const int koff = lane >> 4;                              // 0/1: unit select
    uint32_t a_row[2]; uint32_t a_sw[2];
    #pragma unroll
    for (int mt = 0; mt < 2; mt++) {
        int rr = warpM * 32 + mt * 16 + rit;
        a_row[mt] = abase + (uint32_t)rr * 512u;
        a_sw[mt]  = (uint32_t)(rr & 7);
    }
    const uint32_t ksw = (uint32_t)(rit & 7);
    uint32_t boff[4];
    #pragma unroll
    for (int np = 0; np < 4; np++) {
        uint32_t nunit = (uint32_t)(warpN * 8 + np * 2 + koff);
        boff[np] = ((nunit ^ ksw) << 4);
    }
    const uint32_t browbase = abase + SM_W + (uint32_t)rit * 512u;

    // fragment double buffers: parity = i & 1 (k16_0 is even)
    uint32_t aF[2][2][4];
    uint32_t bF[2][2][4];
    #pragma unroll
    for (int mt = 0; mt < 2; mt++)
        ldsm_x4(aF[0][mt],
                a_row[mt] + (((uint32_t)(k16_0 * 2 + koff) ^ a_sw[mt]) << 4));
    {
        const uint32_t br0 = browbase + (uint32_t)k16_0 * 8192u;
        ldsm_x4_t(bF[0][0], br0 + boff[0]);
        ldsm_x4_t(bF[0][1], br0 + boff[1]);
    }

    #pragma unroll
    for (int i = 0; i < 8; i++) {
        const int k16 = k16_0 + i;
        const int s = i & 1;

        // ---- early global loads (latency hidden behind MMAs) ----
        float kp0, kp1, kp2, kp3;
        float vk0, vk1, vk2, vk3;
        int j0 = 0, jv = 0;
        if (BUILD) {
            int g0 = 2 * (i + 8);
            j0 = 8 * g0 + quad * 2;
            kp0 = g_kpT[j0 * MR + rowb];
            kp1 = g_kpT[(j0 + 1) * MR + rowb];
            kp2 = g_kpT[(j0 + 8) * MR + rowb];
            kp3 = g_kpT[(j0 + 9) * MR + rowb];
        }
        if (VAR) {
            jv = quad * 64 + vbase + i * 4;
            vk0 = g_vkT[jv * MR + rowb];
            vk1 = g_vkT[(jv + 1) * MR + rowb];
            vk2 = g_vkT[(jv + 2) * MR + rowb];
            vk3 = g_vkT[(jv + 3) * MR + rowb];
        }

        // ---- B np=2,3 for current k16 ----
        uint32_t bT[2][4];
        const uint32_t brow = browbase + (uint32_t)k16 * 8192u;
        ldsm_x4_t(bT[0], brow + boff[2]);
        ldsm_x4_t(bT[1], brow + boff[3]);

        // ---- MMA np=0,1 with pre-loaded fragments ----
        #pragma unroll
        for (int mt = 0; mt < 2; mt++) {
            mma_f16(acc[mt][0], aF[s][mt], bF[s][0][0], bF[s][0][1]);
            mma_f16(acc[mt][1], aF[s][mt], bF[s][0][2], bF[s][0][3]);
            mma_f16(acc[mt][2], aF[s][mt], bF[s][1][0], bF[s][1][1]);
            mma_f16(acc[mt][3], aF[s][mt], bF[s][1][2], bF[s][1][3]);
        }

        // ---- prefetch fragments for k16+1 (within this half only) ----
        if (i < 7) {
            #pragma unroll
            for (int mt = 0; mt < 2; mt++) {
                uint32_t unit = (uint32_t)((k16 + 1) * 2 + koff);
                ldsm_x4(aF[s ^ 1][mt], a_row[mt] + ((unit ^ a_sw[mt]) << 4));
            }
            const uint32_t brown = browbase + (uint32_t)(k16 + 1) * 8192u;
            ldsm_x4_t(bF[s ^ 1][0], brown + boff[0]);
            ldsm_x4_t(bF[s ^ 1][1], brown + boff[1]);
        }

        // ---- MMA np=2,3 ----
        #pragma unroll
        for (int mt = 0; mt < 2; mt++) {
            mma_f16(acc[mt][4], aF[s][mt], bT[0][0], bT[0][1]);
            mma_f16(acc[mt][5], aF[s][mt], bT[0][2], bT[0][3]);
            mma_f16(acc[mt][6], aF[s][mt], bT[1][0], bT[1][1]);
            mma_f16(acc[mt][7], aF[s][mt], bT[1][2], bT[1][3]);
        }

        // ---- late: A-build stores + variance FMAs ----
        if (BUILD) {
            int g0 = 2 * (i + 8);
            float v0 = fmaxf(qpb[j0]     + kp0, 0.f);
            float v1 = fmaxf(qpb[j0 + 1] + kp1, 0.f);
            float v2 = fmaxf(qpb[j0 + 8] + kp2, 0.f);
            float v3 = fmaxf(qpb[j0 + 9] + kp3, 0.f);
            a_store_units(smp, m, quad, g0, v0, v1, v2, v3);
        }
        if (VAR) {
            vacc = fmaf(fmaxf(vqb[jv]     + vk0, 0.f), wv2s[jv],     vacc);
            vacc = fmaf(fmaxf(vqb[jv + 1] + vk1, 0.f), wv2s[jv + 1], vacc);
            vacc = fmaf(fmaxf(vqb[jv + 2] + vk2, 0.f), wv2s[jv + 2], vacc);
            vacc = fmaf(fmaxf(vqb[jv + 3] + vk3, 0.f), wv2s[jv + 3], vacc);
        }
    }
}

__global__ __launch_bounds__(512, 1)
void pair_mma_kernel(const float* __restrict__ b1,  const float* __restrict__ b2,
                     const float* __restrict__ b3,  const float* __restrict__ Wf,
                     const float* __restrict__ bfp, const float* __restrict__ bv1,
                     const float* __restrict__ Wv2, const float* __restrict__ bv2,
                     float* __restrict__ out)
{
    extern __shared__ char smraw[];
    const uint32_t smbase = smem_u32(smraw);
    const uint32_t abase  = (smbase + 1023u) & ~1023u;
    char* smp = smraw + (abase - smbase);
    float* qpb  = (float*)(smp + SM_VEC);
    float* vqb  = qpb + 256;
    float* b2s  = vqb + 256;
    float* b3s  = b2s + 256;
    float* wfs  = b3s + 256;
    float* wv2s = wfs + 256;
    float* red  = wv2s + 256;   // 512 floats: [row][warpN]
    float* vred = red + 512;    // 512 floats: [key][p]

    const int tid   = threadIdx.x;
    const int lane  = tid & 31;
    const int w     = tid >> 5;
    const int warpM = w & 3, warpN = w >> 2;
    const int quad  = tid >> 7;
    const int m     = tid & 127;
    const int bid = blockIdx.x;
    const int kt  = bid & 3;
    const int q   = (bid >> 2) & 511;
    const int b   = bid >> 11;
    const int k0  = kt << 7;
    const int rowb  = b * SKK + k0 + m;
    const int lbase = (b * SQ + q) * SKK + k0;

    const char* W2src = (const char*)g_Wh;
    const char* W3src = (const char*)g_Wh + 131072;

    // start W2 copy immediately as two 64KB halves (groups 0,1)
    cp_half(W2src, abase + SM_W, 0, tid);
    cp_half(W2src, abase + SM_W, 1, tid);

    // vectors
    {
        const int r = (b * SQ + q) * HH;
        if (tid < 256) {
            qpb[tid] = g_qp[r + tid] + b1[tid];
            b2s[tid] = b2[tid];
            wfs[tid] = Wf[tid];
        } else {
            int u = tid & 255;
            vqb[u]  = g_vq[r + u] + bv1[u];
            b3s[u]  = b3[u];
            wv2s[u] = Wv2[u];
        }
    }
    __syncthreads();

    // ---- prebuild A slices k16 0..7 only, overlapping the W2 copy ----
    {
        #pragma unroll 4
        for (int gg = 0; gg < 8; gg++) {
            int g0 = gg * 2;
            int j0 = 8 * g0 + quad * 2;
            float v0 = fmaxf(qpb[j0]     + g_kpT[j0 * MR + rowb],       0.f);
            float v1 = fmaxf(qpb[j0 + 1] + g_kpT[(j0 + 1) * MR + rowb], 0.f);
            float v2 = fmaxf(qpb[j0 + 8] + g_kpT[(j0 + 8) * MR + rowb], 0.f);
            float v3 = fmaxf(qpb[j0 + 9] + g_kpT[(j0 + 9) * MR + rowb], 0.f);
            a_store_units(smp, m, quad, g0, v0, v1, v2, v3);
        }
    }
    asm volatile("cp.async.wait_group 1;" ::: "memory");   // W2-lo ready
    __syncthreads();

    // ---- GEMM 1: D = h0 @ W2 ----
    float acc[2][8][4];
    #pragma unroll
    for (int i = 0; i < 2; i++)
        #pragma unroll
        for (int j = 0; j < 8; j++)
            #pragma unroll
            for (int e = 0; e < 4; e++) acc[i][j][e] = 0.f;
    float vacc = 0.f;
    // half1 (k16 0..7, W2 rows 0..127): builds A k16 8..15 + variance j 0..31
    gemm_half<true, true>(abase, 0, warpM, warpN, lane, acc,
                          smp, qpb, vqb, wv2s, rowb, vacc, quad, m, 0);
    asm volatile("cp.async.wait_group 0;" ::: "memory");   // W2-hi ready
    __syncthreads();   // A k16 8..15 visible; W2-lo reads all done
    // W2-lo dead -> stream W3-lo in during half2 (group 2)
    cp_half(W3src, abase + SM_W, 0, tid);
    // half2 (k16 8..15, W2 rows 128..255): variance j 32..63
    gemm_half<false, true>(abase, 8, warpM, warpN, lane, acc,
                           smp, qpb, vqb, wv2s, rowb, vacc, quad, m, 32);
    vred[m * 4 + quad] = vacc;
    __syncthreads();   // all W2 + h0 reads done; vred complete

    // W2-hi dead -> stream W3-hi in during epilogue (group 3)
    cp_half(W3src, abase + SM_W, 1, tid);

    // variance finalize
    if (tid < 128) {
        float s = vred[tid * 4] + vred[tid * 4 + 1] + vred[tid * 4 + 2] + vred[tid * 4 + 3]
                  + bv2[0];
        out[NTOT + lbase + tid] = softplusf(s);
    }

    // ---- epilogue 1: h1 = relu(D + b2) -> A buffer (fp16) ----
    {
        const int g  = lane >> 2;
        const int tg = lane & 3;
        #pragma unroll
        for (int mt = 0; mt < 2; mt++) {
            int r0 = warpM * 32 + mt * 16 + g;
            int r1 = r0 + 8;
            uint32_t row0 = (uint32_t)r0 * 512u;
            uint32_t row1 = (uint32_t)r1 * 512u;
            #pragma unroll
            for (int nt = 0; nt < 8; nt++) {
                int c0 = warpN * 64 + nt * 8 + tg * 2;
                float b20 = b2s[c0], b21 = b2s[c0 + 1];
                float v00 = fmaxf(acc[mt][nt][0] + b20, 0.f);
                float v01 = fmaxf(acc[mt][nt][1] + b21, 0.f);
                float v10 = fmaxf(acc[mt][nt][2] + b20, 0.f);
                float v11 = fmaxf(acc[mt][nt][3] + b21, 0.f);
                uint32_t unit = (uint32_t)(c0 >> 3);
                uint32_t o0 = row0 + ((unit ^ (uint32_t)(r0 & 7)) << 4) + (uint32_t)(tg * 4);
                uint32_t o1 = row1 + ((unit ^ (uint32_t)(r1 & 7)) << 4) + (uint32_t)(tg * 4);
                *(uint32_t*)(smp + SM_A + o0) = f16x2bits(v00, v01);
                *(uint32_t*)(smp + SM_A + o1) = f16x2bits(v10, v11);
            }
        }
    }
    asm volatile("cp.async.wait_group 1;" ::: "memory");   // W3-lo ready
    __syncthreads();

    // ---- GEMM 2: D = h1 @ W3 ----
    #pragma unroll
    for (int i = 0; i < 2; i++)
        #pragma unroll
        for (int j = 0; j < 8; j++)
            #pragma unroll
            for (int e = 0; e < 4; e++) acc[i][j][e] = 0.f;
    gemm_half<false, false>(abase, 0, warpM, warpN, lane, acc,
                            smp, qpb, vqb, wv2s, rowb, vacc, quad, m, 0);
    asm volatile("cp.async.wait_group 0;" ::: "memory");   // W3-hi ready
    __syncthreads();
    gemm_half<false, false>(abase, 8, warpM, warpN, lane, acc,
                            smp, qpb, vqb, wv2s, rowb, vacc, quad, m, 0);

    // ---- epilogue 2: logit = relu(D + b3) . Wf, cross-warp reduce ----
    {
        const int g  = lane >> 2;
        const int tg = lane & 3;
        #pragma unroll
        for (int mt = 0; mt < 2; mt++) {
            float lg0 = 0.f, lg1 = 0.f;
            #pragma unroll
            for (int nt = 0; nt < 8; nt++) {
                int c0 = warpN * 64 + nt * 8 + tg * 2;
                float b30 = b3s[c0], b31 = b3s[c0 + 1];
                float w0  = wfs[c0], w1  = wfs[c0 + 1];
                lg0 = fmaf(fmaxf(acc[mt][nt][0] + b30, 0.f), w0, lg0);
                lg0 = fmaf(fmaxf(acc[mt][nt][1] + b31, 0.f), w1, lg0);
                lg1 = fmaf(fmaxf(acc[mt][nt][2] + b30, 0.f), w0, lg1);
                lg1 = fmaf(fmaxf(acc[mt][nt][3] + b31, 0.f), w1, lg1);
            }
            lg0 += __shfl_xor_sync(0xffffffffu, lg0, 1);
            lg0 += __shfl_xor_sync(0xffffffffu, lg0, 2);
            lg1 += __shfl_xor_sync(0xffffffffu, lg1, 1);
            lg1 += __shfl_xor_sync(0xffffffffu, lg1, 2);
            if (tg == 0) {
                int r0 = warpM * 32 + mt * 16 + g;
                red[r0 * 4 + warpN]       = lg0;
                red[(r0 + 8) * 4 + warpN] = lg1;
            }
        }
    }
    __syncthreads();
    if (tid < 128) {
        float s = red[tid * 4] + red[tid * 4 + 1] + red[tid * 4 + 2] + red[tid * 4 + 3]
                  + bfp[0];
        out[lbase + tid] = s;
    }
}

// ---------------- launcher -----------------------------------------------------
extern "C" void kernel_launch(void* const* d_in, const int* in_sizes, int n_in,
                              void* d_out, int out_size)
{
    const float* query = (const float*)d_in[0];
    const float* key   = (const float*)d_in[1];
    const float* Wqe   = (const float*)d_in[2];
    const float* bqe   = (const float*)d_in[3];
    const float* Wke   = (const float*)d_in[4];
    const float* bke   = (const float*)d_in[5];
    const float* W1    = (const float*)d_in[6];
    const float* b1    = (const float*)d_in[7];
    const float* W2    = (const float*)d_in[8];
    const float* b2    = (const float*)d_in[9];
    const float* W3    = (const float*)d_in[10];
    const float* b3    = (const float*)d_in[11];
    const float* Wf    = (const float*)d_in[12];
    const float* bf    = (const float*)d_in[13];
    const float* Wv1   = (const float*)d_in[14];
    const float* bv1   = (const float*)d_in[15];
    const float* Wv2   = (const float*)d_in[16];
    const float* bv2   = (const float*)d_in[17];
    float* out = (float*)d_out;

    void *p_qf, *p_kf, *p_qp, *p_vq, *p_kpT, *p_vkT;
    cudaGetSymbolAddress(&p_qf,  g_qf);
    cudaGetSymbolAddress(&p_kf,  g_kf);
    cudaGetSymbolAddress(&p_qp,  g_qp);
    cudaGetSymbolAddress(&p_vq,  g_vq);
    cudaGetSymbolAddress(&p_kpT, g_kpT);
    cudaGetSymbolAddress(&p_vkT, g_vkT);

    cudaFuncSetAttribute(proj_batch_kernel,
                         cudaFuncAttributeMaxDynamicSharedMemorySize, PROJ_SMEM_BYTES);

    // launch 1: encoders (z=0,1) + weight convert (z=2)
    ProjJob e0 { query, Wqe, bqe, (float*)p_qf, 0, 1, 0 };
    ProjJob e1 { key,   Wke, bke, (float*)p_kf, 0, 1, 0 };
    proj_batch_kernel<<<dim3(4, 16, 3), 256, PROJ_SMEM_BYTES>>>(
        e0, e1, e0, e0, EE, W2, W3, 2);

    // launch 2: stage-2 projections
    ProjJob s0 { (const float*)p_qf, W1,  nullptr, (float*)p_qp,  0,   0, 0 };
    ProjJob s1 { (const float*)p_kf, W1,  nullptr, (float*)p_kpT, 256, 0, 1 };
    ProjJob s2 { (const float*)p_qf, Wv1, nullptr, (float*)p_vq,  0,   0, 0 };
    ProjJob s3 { (const float*)p_kf, Wv1, nullptr, (float*)p_vkT, 256, 0, 1 };
    proj_batch_kernel<<<dim3(4, 16, 4), 256, PROJ_SMEM_BYTES>>>(
        s0, s1, s2, s3, HH, W2, W3, -1);

    // launch 3: main fused pairwise-MLP kernel (split-layer W streaming)
    cudaFuncSetAttribute(pair_mma_kernel,
                         cudaFuncAttributeMaxDynamicSharedMemorySize, SMEM_BYTES);
    pair_mma_kernel<<<BB * SQ * (SKK / 128), 512, SMEM_BYTES>>>(
        b1, b2, b3, Wf, bf, bv1, Wv2, bv2, out);
}